// round 1
// baseline (speedup 1.0000x reference)
#include <cuda_runtime.h>
#include <math.h>

// Problem constants
#define B_   4
#define SEQ  2048
#define EMB  1024
#define NH   16
#define HD   64
#define SZ   (B_*SEQ*EMB)     // 8,388,608 elements per tensor
#define LOCALK 128
#define SCALE  0.125f         // 1/sqrt(64)
#define NEGF  (-1e30f)

// Scratch (static device arrays: allocation-free per harness rules)
__device__ float g_q[SZ];     // [B*H, SEQ, HD]
__device__ float g_k[SZ];     // [B*H, SEQ, HD]
__device__ float g_v[SZ];     // [B*H, SEQ, HD]
__device__ float g_attn[SZ];  // [B*SEQ, EMB] row-major (attention output, pre-Wo)

// ============================================================================
// GEMM: C[M,N] = A[M,K] @ W[N,K]^T + bias     (M=8192, N=K=1024)
// mode 0: write C row-major [M,N]
// mode 1: scatter to [B,H,t,D] layout (QKV projections)
// a_sel:  0 = A_ext, 1 = g_attn
// dst_sel: 0=g_q 1=g_k 2=g_v 3=out_ext
// ============================================================================
#define BM 128
#define BN 128
#define BK 16
#define TM 8
#define TN 8

__global__ __launch_bounds__(256) void gemm_kernel(
    const float* __restrict__ A_ext, const float* __restrict__ W,
    const float* __restrict__ bias, float* out_ext,
    int a_sel, int dst_sel, int mode)
{
    const float* A = a_sel ? g_attn : A_ext;
    float* C = (dst_sel == 0) ? g_q : (dst_sel == 1) ? g_k
             : (dst_sel == 2) ? g_v : out_ext;

    const int K = EMB, N = EMB;

    __shared__ float As[BK][BM];   // transposed: As[k][m]
    __shared__ float Ws[BK][BN];   // transposed: Ws[k][n]

    int tid = threadIdx.x;
    int tx = tid & 15;             // 0..15 -> output cols tx*8
    int ty = tid >> 4;             // 0..15 -> output rows ty*8
    int mb = blockIdx.y * BM;
    int nb = blockIdx.x * BN;

    float acc[TM][TN];
    #pragma unroll
    for (int i = 0; i < TM; i++)
        #pragma unroll
        for (int j = 0; j < TN; j++) acc[i][j] = 0.f;

    for (int kt = 0; kt < K; kt += BK) {
        // Load 128x16 tiles of A and W (coalesced float4), store transposed.
        #pragma unroll
        for (int l = 0; l < 2; l++) {
            int idx = tid + l * 256;       // 0..511
            int row = idx >> 2;            // 0..127
            int c4  = (idx & 3) << 2;      // 0,4,8,12
            float4 a = *(const float4*)(A + (size_t)(mb + row) * K + kt + c4);
            As[c4+0][row] = a.x; As[c4+1][row] = a.y;
            As[c4+2][row] = a.z; As[c4+3][row] = a.w;
            float4 w = *(const float4*)(W + (size_t)(nb + row) * K + kt + c4);
            Ws[c4+0][row] = w.x; Ws[c4+1][row] = w.y;
            Ws[c4+2][row] = w.z; Ws[c4+3][row] = w.w;
        }
        __syncthreads();

        #pragma unroll
        for (int k = 0; k < BK; k++) {
            float ar[TM], wr[TN];
            *(float4*)&ar[0] = *(const float4*)&As[k][ty*TM];
            *(float4*)&ar[4] = *(const float4*)&As[k][ty*TM + 4];
            *(float4*)&wr[0] = *(const float4*)&Ws[k][tx*TN];
            *(float4*)&wr[4] = *(const float4*)&Ws[k][tx*TN + 4];
            #pragma unroll
            for (int i = 0; i < TM; i++)
                #pragma unroll
                for (int j = 0; j < TN; j++)
                    acc[i][j] = fmaf(ar[i], wr[j], acc[i][j]);
        }
        __syncthreads();
    }

    // Epilogue
    int n0 = nb + tx * TN;
    float bs[TN];
    #pragma unroll
    for (int j = 0; j < TN; j++) bs[j] = bias[n0 + j];

    #pragma unroll
    for (int i = 0; i < TM; i++) {
        int row = mb + ty * TM + i;
        float v[TN];
        #pragma unroll
        for (int j = 0; j < TN; j++) v[j] = acc[i][j] + bs[j];

        float* dst;
        if (mode == 0) {
            dst = C + (size_t)row * N + n0;
        } else {
            // scatter to [B,H,t,D]: row=(b,t), col n0 -> (h, d0); 8-chunk stays in one head
            int bb = row >> 11;            // /2048
            int t  = row & 2047;
            int h  = n0 >> 6;
            int d0 = n0 & 63;
            dst = C + (((size_t)(bb * NH + h) * SEQ + t) * HD + d0);
        }
        ((float4*)dst)[0] = make_float4(v[0], v[1], v[2], v[3]);
        ((float4*)dst)[1] = make_float4(v[4], v[5], v[6], v[7]);
    }
}

// ============================================================================
// Attention: one thread = one query row, flash-style online softmax.
// Block: 128 threads = 128 queries of one (b,h). Key tiles of 32 in smem.
// Local heads (h>0): only key tiles intersecting the |q-k|<=128 band.
// ============================================================================
#define AQ 128
#define AK 32

__global__ __launch_bounds__(128) void attn_kernel()
{
    __shared__ float Ks[AK][HD];
    __shared__ float Vs[AK][HD];
    __shared__ float Ss[AK][AQ];   // per-thread score stash (keeps j-loops rolled)

    int bh = blockIdx.y;                  // 0..63
    int h  = bh & (NH - 1);
    int qt = blockIdx.x;                  // 0..15
    int t  = qt * AQ + threadIdx.x;       // this thread's query index

    const float* qptr = g_q + ((size_t)bh * SEQ + t) * HD;
    float4 q[HD/4];
    #pragma unroll
    for (int i = 0; i < HD/4; i++) q[i] = ((const float4*)qptr)[i];

    float acc[HD];
    #pragma unroll
    for (int d = 0; d < HD; d++) acc[d] = 0.f;
    float m = NEGF, l = 0.f;

    int kt0, kt1;
    if (h == 0) { kt0 = 0; kt1 = SEQ / AK; }
    else {
        int qs = qt * AQ;
        int lo = qs - LOCALK; if (lo < 0) lo = 0;
        int hi = qs + AQ + LOCALK; if (hi > SEQ) hi = SEQ;
        kt0 = lo / AK; kt1 = (hi + AK - 1) / AK;
    }

    for (int kt = kt0; kt < kt1; kt++) {
        int k0 = kt * AK;
        const float* kb = g_k + ((size_t)bh * SEQ + k0) * HD;
        const float* vb = g_v + ((size_t)bh * SEQ + k0) * HD;
        #pragma unroll
        for (int l2 = 0; l2 < 4; l2++) {
            int idx = threadIdx.x + l2 * 128;   // 0..511 (float4 units)
            int r = idx >> 4;
            int c = (idx & 15) << 2;
            *(float4*)&Ks[r][c] = *(const float4*)(kb + r * HD + c);
            *(float4*)&Vs[r][c] = *(const float4*)(vb + r * HD + c);
        }
        __syncthreads();

        // Pass 1: scores + tile max
        float tmax = NEGF;
        for (int j = 0; j < AK; j++) {
            float d0 = 0.f, d1 = 0.f, d2 = 0.f, d3 = 0.f;
            #pragma unroll
            for (int i = 0; i < HD/4; i++) {
                float4 kv = *(const float4*)&Ks[j][4*i];
                d0 = fmaf(q[i].x, kv.x, d0);
                d1 = fmaf(q[i].y, kv.y, d1);
                d2 = fmaf(q[i].z, kv.z, d2);
                d3 = fmaf(q[i].w, kv.w, d3);
            }
            float sv = ((d0 + d1) + (d2 + d3)) * SCALE;
            if (h != 0) {
                int dk = t - (k0 + j);
                if (dk > LOCALK || dk < -LOCALK) sv = NEGF;
            }
            Ss[j][threadIdx.x] = sv;
            tmax = fmaxf(tmax, sv);
        }

        // Online-softmax rescale
        if (tmax > m) {
            float corr = __expf(m - tmax);   // m==NEGF -> corr=0 (correct first time)
            l *= corr;
            #pragma unroll
            for (int d = 0; d < HD; d++) acc[d] *= corr;
            m = tmax;
        }

        // Pass 2: exp + P@V   (skip tiles fully masked for this thread)
        if (tmax > -1e29f) {
            for (int j = 0; j < AK; j++) {
                float p = __expf(Ss[j][threadIdx.x] - m);  // masked -> exp(-huge)=0
                l += p;
                #pragma unroll
                for (int i = 0; i < HD/4; i++) {
                    float4 vv = *(const float4*)&Vs[j][4*i];
                    acc[4*i+0] = fmaf(p, vv.x, acc[4*i+0]);
                    acc[4*i+1] = fmaf(p, vv.y, acc[4*i+1]);
                    acc[4*i+2] = fmaf(p, vv.z, acc[4*i+2]);
                    acc[4*i+3] = fmaf(p, vv.w, acc[4*i+3]);
                }
            }
        }
        __syncthreads();
    }

    // Write O to [B, t, h*64+d] row-major (ready for the Wo GEMM)
    float inv = 1.f / l;
    int bb = bh >> 4;
    float* optr = g_attn + ((size_t)(bb * SEQ + t)) * EMB + h * HD;
    #pragma unroll
    for (int i = 0; i < HD/4; i++) {
        ((float4*)optr)[i] = make_float4(acc[4*i+0]*inv, acc[4*i+1]*inv,
                                         acc[4*i+2]*inv, acc[4*i+3]*inv);
    }
}

// ============================================================================
// Launch
// ============================================================================
extern "C" void kernel_launch(void* const* d_in, const int* in_sizes, int n_in,
                              void* d_out, int out_size)
{
    (void)in_sizes; (void)n_in; (void)out_size;
    const float* x  = (const float*)d_in[0];
    const float* wq = (const float*)d_in[1];
    const float* bq = (const float*)d_in[2];
    const float* wk = (const float*)d_in[3];
    const float* bk = (const float*)d_in[4];
    const float* wv = (const float*)d_in[5];
    const float* bv = (const float*)d_in[6];
    const float* wo = (const float*)d_in[7];
    const float* bo = (const float*)d_in[8];
    float* out = (float*)d_out;

    dim3 gg(EMB / BN, (B_ * SEQ) / BM);   // (8, 64)

    gemm_kernel<<<gg, 256>>>(x, wq, bq, nullptr, 0, 0, 1);   // Q -> g_q [B,H,t,D]
    gemm_kernel<<<gg, 256>>>(x, wk, bk, nullptr, 0, 1, 1);   // K -> g_k
    gemm_kernel<<<gg, 256>>>(x, wv, bv, nullptr, 0, 2, 1);   // V -> g_v

    attn_kernel<<<dim3(SEQ / AQ, B_ * NH), 128>>>();          // -> g_attn [B*t, E]

    gemm_kernel<<<gg, 256>>>(nullptr, wo, bo, out, 1, 3, 0); // O proj -> d_out
}

// round 3
// speedup vs baseline: 1.5171x; 1.5171x over previous
#include <cuda_runtime.h>
#include <cuda_bf16.h>
#include <cstdint>
#include <math.h>

// Problem constants
#define B_   4
#define SEQ  2048
#define EMB  1024
#define NH   16
#define HD   64
#define SZ   (B_*SEQ*EMB)     // 8,388,608
#define LOCALK 128
#define SCALE  0.125f
#define NEGF  (-1e30f)

// Scratch (static device arrays: allocation-free per harness rules)
__device__ float g_q[SZ];
__device__ float g_k[SZ];
__device__ float g_v[SZ];
__device__ float g_attn[SZ];
__device__ __align__(16) __nv_bfloat16 g_xhi[SZ], g_xlo[SZ];
__device__ __align__(16) __nv_bfloat16 g_ahi[SZ], g_alo[SZ];
__device__ __align__(16) __nv_bfloat16 g_whi[4][EMB*EMB], g_wlo[4][EMB*EMB];

// ============================================================================
// Helpers
// ============================================================================
__device__ __forceinline__ uint32_t smem_u32(const void* p) {
    uint32_t a;
    asm("{ .reg .u64 t; cvta.to.shared.u64 t, %1; cvt.u32.u64 %0, t; }" : "=r"(a) : "l"(p));
    return a;
}
#define CP16(dst, src) asm volatile("cp.async.cg.shared.global [%0], [%1], 16;" :: "r"(dst), "l"(src))
#define CP_COMMIT()    asm volatile("cp.async.commit_group;" ::: "memory")
#define CP_WAIT2()     asm volatile("cp.async.wait_group 2;" ::: "memory")
#define CP_WAIT1()     asm volatile("cp.async.wait_group 1;" ::: "memory")
#define CP_WAIT0()     asm volatile("cp.async.wait_group 0;" ::: "memory")

__device__ __forceinline__ void ldsm4(uint32_t addr, uint32_t& r0, uint32_t& r1,
                                      uint32_t& r2, uint32_t& r3) {
    asm volatile("ldmatrix.sync.aligned.m8n8.x4.shared.b16 {%0,%1,%2,%3}, [%4];"
                 : "=r"(r0), "=r"(r1), "=r"(r2), "=r"(r3) : "r"(addr));
}
__device__ __forceinline__ void mma_bf16(float* c, uint32_t a0, uint32_t a1, uint32_t a2,
                                         uint32_t a3, uint32_t b0, uint32_t b1) {
    asm volatile(
        "mma.sync.aligned.m16n8k16.row.col.f32.bf16.bf16.f32 "
        "{%0,%1,%2,%3}, {%4,%5,%6,%7}, {%8,%9}, {%0,%1,%2,%3};"
        : "+f"(c[0]), "+f"(c[1]), "+f"(c[2]), "+f"(c[3])
        : "r"(a0), "r"(a1), "r"(a2), "r"(a3), "r"(b0), "r"(b1));
}

// ============================================================================
// fp32 -> (bf16 hi, bf16 lo) split
// ============================================================================
__global__ __launch_bounds__(256) void split_kernel(const float* __restrict__ src,
                                                    int dsel, int n4) {
    int i = blockIdx.x * 256 + threadIdx.x;
    if (i >= n4) return;
    const float* s = src ? src : g_attn;
    __nv_bfloat16 *hi, *lo;
    if (dsel == 0)      { hi = g_xhi; lo = g_xlo; }
    else if (dsel == 5) { hi = g_ahi; lo = g_alo; }
    else                { hi = g_whi[dsel-1]; lo = g_wlo[dsel-1]; }

    float4 v = ((const float4*)s)[i];
    __nv_bfloat16 h0 = __float2bfloat16(v.x);
    __nv_bfloat16 h1 = __float2bfloat16(v.y);
    __nv_bfloat16 h2 = __float2bfloat16(v.z);
    __nv_bfloat16 h3 = __float2bfloat16(v.w);
    __nv_bfloat16 l0 = __float2bfloat16(v.x - __bfloat162float(h0));
    __nv_bfloat16 l1 = __float2bfloat16(v.y - __bfloat162float(h1));
    __nv_bfloat16 l2 = __float2bfloat16(v.z - __bfloat162float(h2));
    __nv_bfloat16 l3 = __float2bfloat16(v.w - __bfloat162float(h3));
    __nv_bfloat162* H = (__nv_bfloat162*)hi;
    __nv_bfloat162* L = (__nv_bfloat162*)lo;
    H[2*i]   = __nv_bfloat162(h0, h1);
    H[2*i+1] = __nv_bfloat162(h2, h3);
    L[2*i]   = __nv_bfloat162(l0, l1);
    L[2*i+1] = __nv_bfloat162(l2, l3);
}

// ============================================================================
// HMMA split-bf16 GEMM: C[8192,1024] = A @ W^T + bias
// 128x128 tile, BK=32, 3 segments (hi*hi, lo*hi, hi*lo) => 96 k-iterations.
// 3-stage cp.async pipeline. Row stride 40 bf16 (80B) => conflict-free ldmatrix.
// ============================================================================
#define RS    40                    // smem row stride (bf16 elements)
#define STAGEB (128*RS*2)           // bytes per operand tile: 10240
#define STAGE2 (2*STAGEB)           // A+B stage: 20480
#define NSTG  3
#define SMEMB (NSTG*STAGE2)         // 61440
#define NITER 96                    // 3 segments * 32 iters

__global__ __launch_bounds__(256) void gemm_hmma(
    const float* __restrict__ bias, float* __restrict__ out_ext,
    int a_sel, int w_idx, int dst_sel, int scatter)
{
    extern __shared__ char smc[];
    uint32_t smbase = smem_u32(smc);
    int tid = threadIdx.x, lane = tid & 31, wid = tid >> 5;
    int mb = blockIdx.y * 128, nb = blockIdx.x * 128;
    int wm = (wid >> 2) * 64, wn = (wid & 3) * 32;

    const __nv_bfloat16* Ahi = a_sel ? g_ahi : g_xhi;
    const __nv_bfloat16* Alo = a_sel ? g_alo : g_xlo;
    const __nv_bfloat16* Whi = g_whi[w_idx];
    const __nv_bfloat16* Wlo = g_wlo[w_idx];
    float* C = (dst_sel==0) ? g_q : (dst_sel==1) ? g_k : (dst_sel==2) ? g_v : out_ext;

    // Per-thread load coordinates (2 x 16B chunks per operand per stage)
    int r0c = tid >> 2;                 // row of chunk0 (0..63)
    int r1c = (tid + 256) >> 2;         // row of chunk1 (64..127)
    int cc0 = (tid & 3) * 8;            // col element offset

    float acc[4][4][4];
    #pragma unroll
    for (int i = 0; i < 4; i++)
        #pragma unroll
        for (int j = 0; j < 4; j++)
            #pragma unroll
            for (int r = 0; r < 4; r++) acc[i][j][r] = 0.f;

    // Stage function via lambda-ish macro: stage kidx into buffer kidx%3
    auto stage = [&](int kidx) {
        int seg = kidx >> 5;
        int kk  = (kidx & 31) * 32;
        const __nv_bfloat16* As = (seg == 1) ? Alo : Ahi;
        const __nv_bfloat16* Bs = (seg == 2) ? Wlo : Whi;
        uint32_t bufA = smbase + (kidx % 3) * STAGE2;
        uint32_t bufB = bufA + STAGEB;
        const __nv_bfloat16* ap = As + (size_t)mb * EMB + kk;
        const __nv_bfloat16* bp = Bs + (size_t)nb * EMB + kk;
        CP16(bufA + (r0c*RS + cc0)*2, ap + (size_t)r0c*EMB + cc0);
        CP16(bufA + (r1c*RS + cc0)*2, ap + (size_t)r1c*EMB + cc0);
        CP16(bufB + (r0c*RS + cc0)*2, bp + (size_t)r0c*EMB + cc0);
        CP16(bufB + (r1c*RS + cc0)*2, bp + (size_t)r1c*EMB + cc0);
        CP_COMMIT();
    };

    stage(0); stage(1); stage(2);

    // ldmatrix per-lane address components (element offsets)
    int a_row = wm + (lane & 15);               // + mi*16
    int a_half = (lane & 16) ? 8 : 0;           // + kstep*16
    int b_row = wn + (lane & 7) + ((lane & 16) ? 8 : 0);   // + np*16
    int b_half = (lane & 8) ? 8 : 0;            // + kstep*16

    for (int i = 0; i < NITER; i++) {
        if (i >= 1 && i + 2 < NITER) stage(i + 2);
        if (i < NITER-2)      CP_WAIT2();
        else if (i == NITER-2) CP_WAIT1();
        else                  CP_WAIT0();
        __syncthreads();

        uint32_t bufA = smbase + (i % 3) * STAGE2;
        uint32_t bufB = bufA + STAGEB;

        #pragma unroll
        for (int ks = 0; ks < 2; ks++) {
            uint32_t a[4][4], b[2][4];
            #pragma unroll
            for (int mi = 0; mi < 4; mi++)
                ldsm4(bufA + ((a_row + mi*16)*RS + ks*16 + a_half)*2,
                      a[mi][0], a[mi][1], a[mi][2], a[mi][3]);
            #pragma unroll
            for (int np = 0; np < 2; np++)
                ldsm4(bufB + ((b_row + np*16)*RS + ks*16 + b_half)*2,
                      b[np][0], b[np][1], b[np][2], b[np][3]);
            #pragma unroll
            for (int mi = 0; mi < 4; mi++)
                #pragma unroll
                for (int nj = 0; nj < 4; nj++)
                    mma_bf16(acc[mi][nj], a[mi][0], a[mi][1], a[mi][2], a[mi][3],
                             b[nj>>1][(nj&1)*2], b[nj>>1][(nj&1)*2+1]);
        }
        __syncthreads();
    }

    // Epilogue: c0,c1 -> (row, col..col+1); c2,c3 -> (row+8, ...)
    #pragma unroll
    for (int mi = 0; mi < 4; mi++) {
        #pragma unroll
        for (int nj = 0; nj < 4; nj++) {
            int row = mb + wm + mi*16 + (lane >> 2);
            int col = nb + wn + nj*8 + 2*(lane & 3);
            float2 bv = *(const float2*)(bias + col);
            #pragma unroll
            for (int half = 0; half < 2; half++) {
                int rr = row + half*8;
                float2 o = make_float2(acc[mi][nj][2*half+0] + bv.x,
                                       acc[mi][nj][2*half+1] + bv.y);
                float* dst;
                if (!scatter) {
                    dst = C + (size_t)rr * EMB + col;
                } else {
                    int bb = rr >> 11, tt = rr & 2047;
                    int hh = col >> 6, d0 = col & 63;
                    dst = C + (((size_t)(bb*NH + hh) * SEQ + tt) * HD + d0);
                }
                *(float2*)dst = o;
            }
        }
    }
}

// ============================================================================
// Attention (round-1, known-good): one thread = one query, online softmax
// ============================================================================
#define AQ 128
#define AK 32

__global__ __launch_bounds__(128) void attn_kernel()
{
    __shared__ float Ks[AK][HD];
    __shared__ float Vs[AK][HD];
    __shared__ float Ss[AK][AQ];

    int bh = blockIdx.y;
    int h  = bh & (NH - 1);
    int qt = blockIdx.x;
    int t  = qt * AQ + threadIdx.x;

    const float* qptr = g_q + ((size_t)bh * SEQ + t) * HD;
    float4 q[HD/4];
    #pragma unroll
    for (int i = 0; i < HD/4; i++) q[i] = ((const float4*)qptr)[i];

    float acc[HD];
    #pragma unroll
    for (int d = 0; d < HD; d++) acc[d] = 0.f;
    float m = NEGF, l = 0.f;

    int kt0, kt1;
    if (h == 0) { kt0 = 0; kt1 = SEQ / AK; }
    else {
        int qs = qt * AQ;
        int lo = qs - LOCALK; if (lo < 0) lo = 0;
        int hi = qs + AQ + LOCALK; if (hi > SEQ) hi = SEQ;
        kt0 = lo / AK; kt1 = (hi + AK - 1) / AK;
    }

    for (int kt = kt0; kt < kt1; kt++) {
        int k0 = kt * AK;
        const float* kb = g_k + ((size_t)bh * SEQ + k0) * HD;
        const float* vb = g_v + ((size_t)bh * SEQ + k0) * HD;
        #pragma unroll
        for (int l2 = 0; l2 < 4; l2++) {
            int idx = threadIdx.x + l2 * 128;
            int rr = idx >> 4;
            int c = (idx & 15) << 2;
            *(float4*)&Ks[rr][c] = *(const float4*)(kb + rr * HD + c);
            *(float4*)&Vs[rr][c] = *(const float4*)(vb + rr * HD + c);
        }
        __syncthreads();

        float tmax = NEGF;
        for (int j = 0; j < AK; j++) {
            float d0 = 0.f, d1 = 0.f, d2 = 0.f, d3 = 0.f;
            #pragma unroll
            for (int i = 0; i < HD/4; i++) {
                float4 kv = *(const float4*)&Ks[j][4*i];
                d0 = fmaf(q[i].x, kv.x, d0);
                d1 = fmaf(q[i].y, kv.y, d1);
                d2 = fmaf(q[i].z, kv.z, d2);
                d3 = fmaf(q[i].w, kv.w, d3);
            }
            float sv = ((d0 + d1) + (d2 + d3)) * SCALE;
            if (h != 0) {
                int dk = t - (k0 + j);
                if (dk > LOCALK || dk < -LOCALK) sv = NEGF;
            }
            Ss[j][threadIdx.x] = sv;
            tmax = fmaxf(tmax, sv);
        }

        if (tmax > m) {
            float corr = __expf(m - tmax);
            l *= corr;
            #pragma unroll
            for (int d = 0; d < HD; d++) acc[d] *= corr;
            m = tmax;
        }

        if (tmax > -1e29f) {
            for (int j = 0; j < AK; j++) {
                float p = __expf(Ss[j][threadIdx.x] - m);
                l += p;
                #pragma unroll
                for (int i = 0; i < HD/4; i++) {
                    float4 vv = *(const float4*)&Vs[j][4*i];
                    acc[4*i+0] = fmaf(p, vv.x, acc[4*i+0]);
                    acc[4*i+1] = fmaf(p, vv.y, acc[4*i+1]);
                    acc[4*i+2] = fmaf(p, vv.z, acc[4*i+2]);
                    acc[4*i+3] = fmaf(p, vv.w, acc[4*i+3]);
                }
            }
        }
        __syncthreads();
    }

    float inv = 1.f / l;
    int bb = bh >> 4;
    float* optr = g_attn + ((size_t)(bb * SEQ + t)) * EMB + h * HD;
    #pragma unroll
    for (int i = 0; i < HD/4; i++) {
        ((float4*)optr)[i] = make_float4(acc[4*i+0]*inv, acc[4*i+1]*inv,
                                         acc[4*i+2]*inv, acc[4*i+3]*inv);
    }
}

// ============================================================================
// Launch
// ============================================================================
extern "C" void kernel_launch(void* const* d_in, const int* in_sizes, int n_in,
                              void* d_out, int out_size)
{
    (void)in_sizes; (void)n_in; (void)out_size;
    const float* x  = (const float*)d_in[0];
    const float* wq = (const float*)d_in[1];
    const float* bq = (const float*)d_in[2];
    const float* wk = (const float*)d_in[3];
    const float* bk = (const float*)d_in[4];
    const float* wv = (const float*)d_in[5];
    const float* bv = (const float*)d_in[6];
    const float* wo = (const float*)d_in[7];
    const float* bo = (const float*)d_in[8];
    float* out = (float*)d_out;

    cudaFuncSetAttribute(gemm_hmma, cudaFuncAttributeMaxDynamicSharedMemorySize, SMEMB);

    // fp32 -> bf16 hi/lo splits
    split_kernel<<<SZ/4/256, 256>>>(x,  0, SZ/4);
    split_kernel<<<EMB*EMB/4/256, 256>>>(wq, 1, EMB*EMB/4);
    split_kernel<<<EMB*EMB/4/256, 256>>>(wk, 2, EMB*EMB/4);
    split_kernel<<<EMB*EMB/4/256, 256>>>(wv, 3, EMB*EMB/4);
    split_kernel<<<EMB*EMB/4/256, 256>>>(wo, 4, EMB*EMB/4);

    dim3 gg(EMB/128, (B_*SEQ)/128);   // (8, 64)
    gemm_hmma<<<gg, 256, SMEMB>>>(bq, nullptr, 0, 0, 0, 1);  // Q -> g_q (scatter)
    gemm_hmma<<<gg, 256, SMEMB>>>(bk, nullptr, 0, 1, 1, 1);  // K -> g_k
    gemm_hmma<<<gg, 256, SMEMB>>>(bv, nullptr, 0, 2, 2, 1);  // V -> g_v

    attn_kernel<<<dim3(SEQ/AQ, B_*NH), 128>>>();             // -> g_attn

    split_kernel<<<SZ/4/256, 256>>>(nullptr, 5, SZ/4);       // g_attn -> hi/lo
    gemm_hmma<<<gg, 256, SMEMB>>>(bo, out, 1, 3, 3, 0);      // O proj -> d_out
}

// round 5
// speedup vs baseline: 2.7051x; 1.7831x over previous
#include <cuda_runtime.h>
#include <cuda_bf16.h>
#include <cstdint>
#include <math.h>

// Problem constants
#define B_   4
#define SEQ  2048
#define EMB  1024
#define NH   16
#define HD   64
#define SZ   (B_*SEQ*EMB)     // 8,388,608
#define LOCALK 128
#define SCALE  0.125f
#define NEGF  (-1e30f)

// Scratch (static device arrays)
__device__ __align__(16) __nv_bfloat16 g_xhi[SZ], g_xlo[SZ];     // x split
__device__ __align__(16) __nv_bfloat16 g_ahi[SZ], g_alo[SZ];     // attn out split
__device__ __align__(16) __nv_bfloat16 g_whi[4][EMB*EMB], g_wlo[4][EMB*EMB];
__device__ __align__(16) __nv_bfloat16 g_qhi[SZ], g_qlo[SZ];     // [bh][t][d], pre-scaled
__device__ __align__(16) __nv_bfloat16 g_khi[SZ], g_klo[SZ];     // [bh][t][d]
__device__ __align__(16) __nv_bfloat16 g_vthi[SZ], g_vtlo[SZ];   // [bh][d][t]  (transposed)

// ============================================================================
// Helpers
// ============================================================================
__device__ __forceinline__ uint32_t smem_u32(const void* p) {
    uint32_t a;
    asm("{ .reg .u64 t; cvta.to.shared.u64 t, %1; cvt.u32.u64 %0, t; }" : "=r"(a) : "l"(p));
    return a;
}
#define CP16(dst, src) asm volatile("cp.async.cg.shared.global [%0], [%1], 16;" :: "r"(dst), "l"(src))
#define CP_COMMIT()    asm volatile("cp.async.commit_group;" ::: "memory")
#define CP_WAIT1()     asm volatile("cp.async.wait_group 1;" ::: "memory")
#define CP_WAIT0()     asm volatile("cp.async.wait_group 0;" ::: "memory")

__device__ __forceinline__ void ldsm4(uint32_t addr, uint32_t* r) {
    asm volatile("ldmatrix.sync.aligned.m8n8.x4.shared.b16 {%0,%1,%2,%3}, [%4];"
                 : "=r"(r[0]), "=r"(r[1]), "=r"(r[2]), "=r"(r[3]) : "r"(addr));
}
__device__ __forceinline__ void mma_bf16(float* c, uint32_t a0, uint32_t a1, uint32_t a2,
                                         uint32_t a3, uint32_t b0, uint32_t b1) {
    asm volatile(
        "mma.sync.aligned.m16n8k16.row.col.f32.bf16.bf16.f32 "
        "{%0,%1,%2,%3}, {%4,%5,%6,%7}, {%8,%9}, {%0,%1,%2,%3};"
        : "+f"(c[0]), "+f"(c[1]), "+f"(c[2]), "+f"(c[3])
        : "r"(a0), "r"(a1), "r"(a2), "r"(a3), "r"(b0), "r"(b1));
}
// {lo16 = a.hi16, hi16 = b.hi16}  (pack bf16 truncations of a,b; a -> low element)
__device__ __forceinline__ uint32_t prmt_hi(float a, float b) {
    uint32_t d;
    asm("prmt.b32 %0, %1, %2, 0x7632;" : "=r"(d) : "r"(__float_as_uint(a)), "r"(__float_as_uint(b)));
    return d;
}
// packed bf16x2 with rounding: element0 = lo, element1 = hi
__device__ __forceinline__ uint32_t packbf(float lo, float hi) {
    uint32_t d;
    asm("cvt.rn.bf16x2.f32 %0, %1, %2;" : "=r"(d) : "f"(hi), "f"(lo));
    return d;
}
__device__ __forceinline__ float truncbf(float v) {
    return __uint_as_float(__float_as_uint(v) & 0xFFFF0000u);
}

// ============================================================================
// fp32 -> (bf16 hi, bf16 lo) split   dsel: 0=x, 1..4=weights
// ============================================================================
__global__ __launch_bounds__(256) void split_kernel(const float* __restrict__ src,
                                                    int dsel, int n4) {
    int i = blockIdx.x * 256 + threadIdx.x;
    if (i >= n4) return;
    __nv_bfloat16 *hi, *lo;
    if (dsel == 0) { hi = g_xhi; lo = g_xlo; }
    else           { hi = g_whi[dsel-1]; lo = g_wlo[dsel-1]; }

    float4 v = ((const float4*)src)[i];
    __nv_bfloat16 h0 = __float2bfloat16(v.x), h1 = __float2bfloat16(v.y);
    __nv_bfloat16 h2 = __float2bfloat16(v.z), h3 = __float2bfloat16(v.w);
    __nv_bfloat16 l0 = __float2bfloat16(v.x - __bfloat162float(h0));
    __nv_bfloat16 l1 = __float2bfloat16(v.y - __bfloat162float(h1));
    __nv_bfloat16 l2 = __float2bfloat16(v.z - __bfloat162float(h2));
    __nv_bfloat16 l3 = __float2bfloat16(v.w - __bfloat162float(h3));
    __nv_bfloat162* H = (__nv_bfloat162*)hi;
    __nv_bfloat162* L = (__nv_bfloat162*)lo;
    H[2*i]   = __nv_bfloat162(h0, h1);  H[2*i+1] = __nv_bfloat162(h2, h3);
    L[2*i]   = __nv_bfloat162(l0, l1);  L[2*i+1] = __nv_bfloat162(l2, l3);
}

// ============================================================================
// HMMA split-bf16 GEMM: C[8192,1024] = A @ W^T + bias
// 128x128 tile, BK=32, fused 3-pass per chunk (Ahi*Bhi + Alo*Bhi + Ahi*Blo).
// 3-stage pipeline (Ahi,Alo,Bhi,Blo per stage), ONE syncthreads per iter.
// dst_sel: 0=Q(split,scaled) 1=K(split) 2=V(split,transposed) 3=fp32 out
// ============================================================================
#define RS    40
#define GTB   (128*RS*2)          // 10240 bytes per tile
#define GSTG  (4*GTB)             // 40960 per stage
#define GSMEM (3*GSTG)            // 122880
#define GNIT  32                  // 1024/32 chunks

__global__ __launch_bounds__(256) void gemm_hmma(
    const float* __restrict__ bias, float* __restrict__ out_ext,
    int a_sel, int w_idx, int dst_sel)
{
    extern __shared__ char smc[];
    uint32_t smbase = smem_u32(smc);
    int tid = threadIdx.x, lane = tid & 31, wid = tid >> 5;
    int mb = blockIdx.y * 128, nb = blockIdx.x * 128;
    int wm = (wid >> 2) * 64, wn = (wid & 3) * 32;

    const __nv_bfloat16* Ahi = a_sel ? g_ahi : g_xhi;
    const __nv_bfloat16* Alo = a_sel ? g_alo : g_xlo;
    const __nv_bfloat16* Bhi = g_whi[w_idx];
    const __nv_bfloat16* Blo = g_wlo[w_idx];

    int r0c = tid >> 2;                  // 0..63
    int r1c = r0c + 64;                  // 64..127
    int cc0 = (tid & 3) * 8;             // 0,8,16,24

    float acc[4][4][4];
    #pragma unroll
    for (int i = 0; i < 4; i++)
        #pragma unroll
        for (int j = 0; j < 4; j++)
            #pragma unroll
            for (int r = 0; r < 4; r++) acc[i][j][r] = 0.f;

    auto stage = [&](int kidx) {
        int kk = kidx * 32;
        uint32_t buf = smbase + (kidx % 3) * GSTG;
        const __nv_bfloat16* p0 = Ahi + (size_t)mb * EMB + kk;
        const __nv_bfloat16* p1 = Alo + (size_t)mb * EMB + kk;
        const __nv_bfloat16* p2 = Bhi + (size_t)nb * EMB + kk;
        const __nv_bfloat16* p3 = Blo + (size_t)nb * EMB + kk;
        CP16(buf + 0*GTB + (r0c*RS + cc0)*2, p0 + (size_t)r0c*EMB + cc0);
        CP16(buf + 0*GTB + (r1c*RS + cc0)*2, p0 + (size_t)r1c*EMB + cc0);
        CP16(buf + 1*GTB + (r0c*RS + cc0)*2, p1 + (size_t)r0c*EMB + cc0);
        CP16(buf + 1*GTB + (r1c*RS + cc0)*2, p1 + (size_t)r1c*EMB + cc0);
        CP16(buf + 2*GTB + (r0c*RS + cc0)*2, p2 + (size_t)r0c*EMB + cc0);
        CP16(buf + 2*GTB + (r1c*RS + cc0)*2, p2 + (size_t)r1c*EMB + cc0);
        CP16(buf + 3*GTB + (r0c*RS + cc0)*2, p3 + (size_t)r0c*EMB + cc0);
        CP16(buf + 3*GTB + (r1c*RS + cc0)*2, p3 + (size_t)r1c*EMB + cc0);
        CP_COMMIT();
    };

    stage(0); stage(1);

    int a_row = wm + (lane & 15);
    int a_half = (lane & 16) ? 8 : 0;
    int b_row = wn + (lane & 7) + ((lane & 16) ? 8 : 0);
    int b_half = (lane & 8) ? 8 : 0;

    for (int i = 0; i < GNIT; i++) {
        if (i == GNIT-1) CP_WAIT0(); else CP_WAIT1();
        __syncthreads();
        if (i + 2 < GNIT) stage(i + 2);

        uint32_t buf = smbase + (i % 3) * GSTG;
        #pragma unroll
        for (int ks = 0; ks < 2; ks++) {
            uint32_t ah[4][4], al[4][4], bh[2][4], bl[2][4];
            #pragma unroll
            for (int mi = 0; mi < 4; mi++) {
                uint32_t off = ((a_row + mi*16)*RS + ks*16 + a_half)*2;
                ldsm4(buf + 0*GTB + off, ah[mi]);
                ldsm4(buf + 1*GTB + off, al[mi]);
            }
            #pragma unroll
            for (int np = 0; np < 2; np++) {
                uint32_t off = ((b_row + np*16)*RS + ks*16 + b_half)*2;
                ldsm4(buf + 2*GTB + off, bh[np]);
                ldsm4(buf + 3*GTB + off, bl[np]);
            }
            #pragma unroll
            for (int mi = 0; mi < 4; mi++)
                #pragma unroll
                for (int nj = 0; nj < 4; nj++) {
                    uint32_t b0 = bh[nj>>1][(nj&1)*2], b1 = bh[nj>>1][(nj&1)*2+1];
                    mma_bf16(acc[mi][nj], ah[mi][0], ah[mi][1], ah[mi][2], ah[mi][3], b0, b1);
                    mma_bf16(acc[mi][nj], al[mi][0], al[mi][1], al[mi][2], al[mi][3], b0, b1);
                    uint32_t c0 = bl[nj>>1][(nj&1)*2], c1 = bl[nj>>1][(nj&1)*2+1];
                    mma_bf16(acc[mi][nj], ah[mi][0], ah[mi][1], ah[mi][2], ah[mi][3], c0, c1);
                }
        }
    }

    // Epilogue
    #pragma unroll
    for (int mi = 0; mi < 4; mi++) {
        #pragma unroll
        for (int nj = 0; nj < 4; nj++) {
            int row = mb + wm + mi*16 + (lane >> 2);
            int col = nb + wn + nj*8 + 2*(lane & 3);
            float2 bv = *(const float2*)(bias + col);
            #pragma unroll
            for (int half = 0; half < 2; half++) {
                int rr = row + half*8;
                float v0 = acc[mi][nj][2*half+0] + bv.x;
                float v1 = acc[mi][nj][2*half+1] + bv.y;
                if (dst_sel == 3) {
                    *(float2*)(out_ext + (size_t)rr * EMB + col) = make_float2(v0, v1);
                    continue;
                }
                int bb = rr >> 11, tt = rr & 2047;
                int hh = col >> 6, d0 = col & 63;
                if (dst_sel == 0) { v0 *= SCALE; v1 *= SCALE; }
                __nv_bfloat16 h0 = __float2bfloat16(v0), h1 = __float2bfloat16(v1);
                __nv_bfloat16 l0 = __float2bfloat16(v0 - __bfloat162float(h0));
                __nv_bfloat16 l1 = __float2bfloat16(v1 - __bfloat162float(h1));
                if (dst_sel == 2) {
                    // transposed: vt[bh][d][t]
                    size_t base = ((size_t)(bb*NH + hh) * HD + d0) * SEQ + tt;
                    g_vthi[base] = h0;  g_vthi[base + SEQ] = h1;
                    g_vtlo[base] = l0;  g_vtlo[base + SEQ] = l1;
                } else {
                    size_t base = ((size_t)(bb*NH + hh) * SEQ + tt) * HD + d0;
                    __nv_bfloat16* Hd = dst_sel ? g_khi : g_qhi;
                    __nv_bfloat16* Ld = dst_sel ? g_klo : g_qlo;
                    *(__nv_bfloat162*)(Hd + base) = __nv_bfloat162(h0, h1);
                    *(__nv_bfloat162*)(Ld + base) = __nv_bfloat162(l0, l1);
                }
            }
        }
    }
}

// ============================================================================
// Tensor-core attention: Q-tile 64, K-tile 64, 4 warps (16 q-rows each).
// S = Q@K^T (3-pass split-bf16, Q pre-scaled), online softmax in fp32 frags,
// O += P@Vt (3-pass split; P split by truncation). Writes split-bf16 attn-out.
// ============================================================================
#define QT   64
#define KT   64
#define RSA  72
#define AQB  (64*RSA*2)           // 9216 bytes per 64x64(+pad) tile
#define ASTG (4*AQB)              // 36864 (Khi,Klo,Vhi,Vlo)
#define ASMEM (2*AQB + 2*ASTG)    // 92160

__global__ __launch_bounds__(128) void attn_tc()
{
    extern __shared__ char smc[];
    uint32_t sb = smem_u32(smc);
    int tid = threadIdx.x, lane = tid & 31, wid = tid >> 5;
    int bh = blockIdx.y, h = bh & (NH-1), bb = bh >> 4;
    int q0 = blockIdx.x * QT;

    const __nv_bfloat16* Qhp = g_qhi + ((size_t)bh*SEQ + q0) * HD;
    const __nv_bfloat16* Qlp = g_qlo + ((size_t)bh*SEQ + q0) * HD;
    const __nv_bfloat16* Khp = g_khi + (size_t)bh*SEQ*HD;
    const __nv_bfloat16* Klp = g_klo + (size_t)bh*SEQ*HD;
    const __nv_bfloat16* Vhp = g_vthi + (size_t)bh*SEQ*HD;   // [d][t]
    const __nv_bfloat16* Vlp = g_vtlo + (size_t)bh*SEQ*HD;

    // K-tile range
    int kt0, kt1;
    if (h == 0) { kt0 = 0; kt1 = SEQ / KT; }
    else {
        int lo = q0 - LOCALK; if (lo < 0) lo = 0;
        int hi = q0 + QT + LOCALK; if (hi > SEQ) hi = SEQ;
        kt0 = lo / KT; kt1 = hi / KT;
    }
    int nkt = kt1 - kt0;

    auto stage_kv = [&](int buf, int ktile) {
        uint32_t stg = sb + 2*AQB + buf*ASTG;
        int k0 = ktile * KT;
        #pragma unroll
        for (int j = 0; j < 4; j++) {
            int idx = tid + j*128;
            int r = idx >> 3, c = (idx & 7) * 8;
            uint32_t off = (uint32_t)(r*RSA + c) * 2;
            CP16(stg + 0*AQB + off, Khp + (size_t)(k0 + r)*HD + c);
            CP16(stg + 1*AQB + off, Klp + (size_t)(k0 + r)*HD + c);
            CP16(stg + 2*AQB + off, Vhp + (size_t)r*SEQ + k0 + c);
            CP16(stg + 3*AQB + off, Vlp + (size_t)r*SEQ + k0 + c);
        }
    };

    // Load Q tile + stage 0 in one group
    #pragma unroll
    for (int j = 0; j < 4; j++) {
        int idx = tid + j*128;
        int r = idx >> 3, c = (idx & 7) * 8;
        uint32_t off = (uint32_t)(r*RSA + c) * 2;
        CP16(sb + 0   + off, Qhp + (size_t)r*HD + c);
        CP16(sb + AQB + off, Qlp + (size_t)r*HD + c);
    }
    stage_kv(0, kt0);
    CP_COMMIT();

    uint32_t a_off = (uint32_t)((wid*16 + (lane & 15))*RSA + ((lane & 16) ? 8 : 0)) * 2;
    int b_row = (lane & 7) + ((lane & 16) ? 8 : 0);
    int b_half = (lane & 8) ? 8 : 0;
    int r0g = q0 + wid*16 + (lane >> 2);      // global q row for regs 0,1 (+8 for 2,3)

    float o[8][4];
    #pragma unroll
    for (int nj = 0; nj < 8; nj++)
        #pragma unroll
        for (int r = 0; r < 4; r++) o[nj][r] = 0.f;
    float m0 = NEGF, m1 = NEGF, l0 = 0.f, l1 = 0.f;
    uint32_t qh[4][4], ql[4][4];

    for (int it = 0; it < nkt; it++) {
        uint32_t stg = sb + 2*AQB + (it & 1)*ASTG;
        if (it + 1 < nkt) { stage_kv((it+1) & 1, kt0 + it + 1); CP_COMMIT(); CP_WAIT1(); }
        else CP_WAIT0();
        __syncthreads();

        if (it == 0) {
            #pragma unroll
            for (int ks = 0; ks < 4; ks++) {
                ldsm4(sb + 0   + a_off + ks*32, qh[ks]);
                ldsm4(sb + AQB + a_off + ks*32, ql[ks]);
            }
        }

        // ---- S = Q@K^T (3 passes) ----
        float s[8][4];
        #pragma unroll
        for (int nj = 0; nj < 8; nj++)
            #pragma unroll
            for (int r = 0; r < 4; r++) s[nj][r] = 0.f;

        #pragma unroll
        for (int ks = 0; ks < 4; ks++) {
            uint32_t b[4][4];
            #pragma unroll
            for (int np = 0; np < 4; np++)
                ldsm4(stg + 0*AQB + ((b_row + np*16)*RSA + ks*16 + b_half)*2, b[np]);
            #pragma unroll
            for (int nj = 0; nj < 8; nj++) {
                uint32_t b0 = b[nj>>1][(nj&1)*2], b1 = b[nj>>1][(nj&1)*2+1];
                mma_bf16(s[nj], qh[ks][0], qh[ks][1], qh[ks][2], qh[ks][3], b0, b1);
                mma_bf16(s[nj], ql[ks][0], ql[ks][1], ql[ks][2], ql[ks][3], b0, b1);
            }
        }
        #pragma unroll
        for (int ks = 0; ks < 4; ks++) {
            uint32_t b[4][4];
            #pragma unroll
            for (int np = 0; np < 4; np++)
                ldsm4(stg + 1*AQB + ((b_row + np*16)*RSA + ks*16 + b_half)*2, b[np]);
            #pragma unroll
            for (int nj = 0; nj < 8; nj++)
                mma_bf16(s[nj], qh[ks][0], qh[ks][1], qh[ks][2], qh[ks][3],
                         b[nj>>1][(nj&1)*2], b[nj>>1][(nj&1)*2+1]);
        }

        int k0 = (kt0 + it) * KT;
        // ---- mask (local heads) ----
        if (h != 0) {
            #pragma unroll
            for (int nj = 0; nj < 8; nj++) {
                int c0 = k0 + nj*8 + 2*(lane & 3);
                if (abs(r0g - c0)     > LOCALK) s[nj][0] = NEGF;
                if (abs(r0g - c0 - 1) > LOCALK) s[nj][1] = NEGF;
                if (abs(r0g + 8 - c0)     > LOCALK) s[nj][2] = NEGF;
                if (abs(r0g + 8 - c0 - 1) > LOCALK) s[nj][3] = NEGF;
            }
        }

        // ---- online softmax ----
        float mx0 = NEGF, mx1 = NEGF;
        #pragma unroll
        for (int nj = 0; nj < 8; nj++) {
            mx0 = fmaxf(mx0, fmaxf(s[nj][0], s[nj][1]));
            mx1 = fmaxf(mx1, fmaxf(s[nj][2], s[nj][3]));
        }
        mx0 = fmaxf(mx0, __shfl_xor_sync(0xffffffffu, mx0, 1));
        mx0 = fmaxf(mx0, __shfl_xor_sync(0xffffffffu, mx0, 2));
        mx1 = fmaxf(mx1, __shfl_xor_sync(0xffffffffu, mx1, 1));
        mx1 = fmaxf(mx1, __shfl_xor_sync(0xffffffffu, mx1, 2));
        float nm0 = fmaxf(m0, mx0), nm1 = fmaxf(m1, mx1);
        float cr0 = __expf(m0 - nm0), cr1 = __expf(m1 - nm1);
        m0 = nm0; m1 = nm1; l0 *= cr0; l1 *= cr1;
        #pragma unroll
        for (int nj = 0; nj < 8; nj++) {
            o[nj][0] *= cr0; o[nj][1] *= cr0;
            o[nj][2] *= cr1; o[nj][3] *= cr1;
        }
        float rs0 = 0.f, rs1 = 0.f;
        #pragma unroll
        for (int nj = 0; nj < 8; nj++) {
            float p0 = __expf(s[nj][0] - m0), p1 = __expf(s[nj][1] - m0);
            float p2 = __expf(s[nj][2] - m1), p3 = __expf(s[nj][3] - m1);
            rs0 += p0 + p1; rs1 += p2 + p3;
            // pack: hi via truncation, lo via rounded residual
            uint32_t h01 = prmt_hi(p0, p1), h23 = prmt_hi(p2, p3);
            uint32_t lo01 = packbf(p0 - truncbf(p0), p1 - truncbf(p1));
            uint32_t lo23 = packbf(p2 - truncbf(p2), p3 - truncbf(p3));
            s[nj][0] = __uint_as_float(h01);  s[nj][1] = __uint_as_float(h23);
            s[nj][2] = __uint_as_float(lo01); s[nj][3] = __uint_as_float(lo23);
        }
        rs0 += __shfl_xor_sync(0xffffffffu, rs0, 1);
        rs0 += __shfl_xor_sync(0xffffffffu, rs0, 2);
        rs1 += __shfl_xor_sync(0xffffffffu, rs1, 1);
        rs1 += __shfl_xor_sync(0xffffffffu, rs1, 2);
        l0 += rs0; l1 += rs1;

        // ---- O += P @ Vt (3 passes) ----
        #pragma unroll
        for (int kc = 0; kc < 4; kc++) {
            uint32_t ah0 = __float_as_uint(s[2*kc][0]),   ah1 = __float_as_uint(s[2*kc][1]);
            uint32_t ah2 = __float_as_uint(s[2*kc+1][0]), ah3 = __float_as_uint(s[2*kc+1][1]);
            uint32_t al0 = __float_as_uint(s[2*kc][2]),   al1 = __float_as_uint(s[2*kc][3]);
            uint32_t al2 = __float_as_uint(s[2*kc+1][2]), al3 = __float_as_uint(s[2*kc+1][3]);
            uint32_t b[4][4];
            #pragma unroll
            for (int np = 0; np < 4; np++)
                ldsm4(stg + 2*AQB + ((b_row + np*16)*RSA + kc*16 + b_half)*2, b[np]);
            #pragma unroll
            for (int nj = 0; nj < 8; nj++) {
                uint32_t b0 = b[nj>>1][(nj&1)*2], b1 = b[nj>>1][(nj&1)*2+1];
                mma_bf16(o[nj], ah0, ah1, ah2, ah3, b0, b1);
                mma_bf16(o[nj], al0, al1, al2, al3, b0, b1);
            }
            #pragma unroll
            for (int np = 0; np < 4; np++)
                ldsm4(stg + 3*AQB + ((b_row + np*16)*RSA + kc*16 + b_half)*2, b[np]);
            #pragma unroll
            for (int nj = 0; nj < 8; nj++)
                mma_bf16(o[nj], ah0, ah1, ah2, ah3,
                         b[nj>>1][(nj&1)*2], b[nj>>1][(nj&1)*2+1]);
        }
        __syncthreads();
    }

    // ---- epilogue: normalize, split, store ----
    float inv0 = 1.f / l0, inv1 = 1.f / l1;
    #pragma unroll
    for (int nj = 0; nj < 8; nj++) {
        int d = nj*8 + 2*(lane & 3);
        float v0 = o[nj][0]*inv0, v1 = o[nj][1]*inv0;
        float v2 = o[nj][2]*inv1, v3 = o[nj][3]*inv1;
        uint32_t h01 = prmt_hi(v0, v1), h23 = prmt_hi(v2, v3);
        uint32_t lo01 = packbf(v0 - truncbf(v0), v1 - truncbf(v1));
        uint32_t lo23 = packbf(v2 - truncbf(v2), v3 - truncbf(v3));
        size_t base0 = ((size_t)(bb*SEQ + r0g)) * EMB + h*HD + d;
        size_t base1 = ((size_t)(bb*SEQ + r0g + 8)) * EMB + h*HD + d;
        *(uint32_t*)(g_ahi + base0) = h01;
        *(uint32_t*)(g_alo + base0) = lo01;
        *(uint32_t*)(g_ahi + base1) = h23;
        *(uint32_t*)(g_alo + base1) = lo23;
    }
}

// ============================================================================
// Launch
// ============================================================================
extern "C" void kernel_launch(void* const* d_in, const int* in_sizes, int n_in,
                              void* d_out, int out_size)
{
    (void)in_sizes; (void)n_in; (void)out_size;
    const float* x  = (const float*)d_in[0];
    const float* wq = (const float*)d_in[1];
    const float* bq = (const float*)d_in[2];
    const float* wk = (const float*)d_in[3];
    const float* bk = (const float*)d_in[4];
    const float* wv = (const float*)d_in[5];
    const float* bv = (const float*)d_in[6];
    const float* wo = (const float*)d_in[7];
    const float* bo = (const float*)d_in[8];
    float* out = (float*)d_out;

    cudaFuncSetAttribute(gemm_hmma, cudaFuncAttributeMaxDynamicSharedMemorySize, GSMEM);
    cudaFuncSetAttribute(attn_tc,   cudaFuncAttributeMaxDynamicSharedMemorySize, ASMEM);

    split_kernel<<<SZ/4/256, 256>>>(x,  0, SZ/4);
    split_kernel<<<EMB*EMB/4/256, 256>>>(wq, 1, EMB*EMB/4);
    split_kernel<<<EMB*EMB/4/256, 256>>>(wk, 2, EMB*EMB/4);
    split_kernel<<<EMB*EMB/4/256, 256>>>(wv, 3, EMB*EMB/4);
    split_kernel<<<EMB*EMB/4/256, 256>>>(wo, 4, EMB*EMB/4);

    dim3 gg(EMB/128, (B_*SEQ)/128);   // (8, 64)
    gemm_hmma<<<gg, 256, GSMEM>>>(bq, nullptr, 0, 0, 0);  // Q (split+scale)
    gemm_hmma<<<gg, 256, GSMEM>>>(bk, nullptr, 0, 1, 1);  // K (split)
    gemm_hmma<<<gg, 256, GSMEM>>>(bv, nullptr, 0, 2, 2);  // V (split+transpose)

    attn_tc<<<dim3(SEQ/QT, B_*NH), 128, ASMEM>>>();       // -> g_ahi/g_alo

    gemm_hmma<<<gg, 256, GSMEM>>>(bo, out, 1, 3, 3);      // O proj -> d_out
}

// round 6
// speedup vs baseline: 4.2438x; 1.5688x over previous
#include <cuda_runtime.h>
#include <cuda_bf16.h>
#include <cuda_fp16.h>
#include <cstdint>
#include <math.h>

// Problem constants
#define B_   4
#define SEQ  2048
#define EMB  1024
#define NH   16
#define HD   64
#define SZ   (B_*SEQ*EMB)     // 8,388,608
#define LOCALK 128
#define SCALE  0.125f
#define NEGF  (-1e30f)

// Scratch
__device__ __align__(16) __half g_xhi[SZ], g_xlo[SZ];            // x split (fp16)
__device__ __align__(16) __half g_ahi[SZ], g_alo[SZ];            // attn out split (fp16)
__device__ __align__(16) __half g_wh[4][EMB*EMB];                // weights (fp16)
__device__ __align__(16) __nv_bfloat16 g_qhi[SZ], g_qlo[SZ];     // [bh][t][d], pre-scaled
__device__ __align__(16) __nv_bfloat16 g_khi[SZ], g_klo[SZ];     // [bh][t][d]
__device__ __align__(16) __nv_bfloat16 g_vthi[SZ], g_vtlo[SZ];   // [bh][d][t]

// ============================================================================
// Helpers
// ============================================================================
__device__ __forceinline__ uint32_t smem_u32(const void* p) {
    uint32_t a;
    asm("{ .reg .u64 t; cvta.to.shared.u64 t, %1; cvt.u32.u64 %0, t; }" : "=r"(a) : "l"(p));
    return a;
}
#define CP16(dst, src) asm volatile("cp.async.cg.shared.global [%0], [%1], 16;" :: "r"(dst), "l"(src))
#define CP_COMMIT()    asm volatile("cp.async.commit_group;" ::: "memory")
#define CP_WAIT1()     asm volatile("cp.async.wait_group 1;" ::: "memory")
#define CP_WAIT0()     asm volatile("cp.async.wait_group 0;" ::: "memory")

__device__ __forceinline__ void ldsm4(uint32_t addr, uint32_t* r) {
    asm volatile("ldmatrix.sync.aligned.m8n8.x4.shared.b16 {%0,%1,%2,%3}, [%4];"
                 : "=r"(r[0]), "=r"(r[1]), "=r"(r[2]), "=r"(r[3]) : "r"(addr));
}
__device__ __forceinline__ void mma_bf16(float* c, uint32_t a0, uint32_t a1, uint32_t a2,
                                         uint32_t a3, uint32_t b0, uint32_t b1) {
    asm volatile(
        "mma.sync.aligned.m16n8k16.row.col.f32.bf16.bf16.f32 "
        "{%0,%1,%2,%3}, {%4,%5,%6,%7}, {%8,%9}, {%0,%1,%2,%3};"
        : "+f"(c[0]), "+f"(c[1]), "+f"(c[2]), "+f"(c[3])
        : "r"(a0), "r"(a1), "r"(a2), "r"(a3), "r"(b0), "r"(b1));
}
__device__ __forceinline__ void mma_f16(float* c, uint32_t a0, uint32_t a1, uint32_t a2,
                                        uint32_t a3, uint32_t b0, uint32_t b1) {
    asm volatile(
        "mma.sync.aligned.m16n8k16.row.col.f32.f16.f16.f32 "
        "{%0,%1,%2,%3}, {%4,%5,%6,%7}, {%8,%9}, {%0,%1,%2,%3};"
        : "+f"(c[0]), "+f"(c[1]), "+f"(c[2]), "+f"(c[3])
        : "r"(a0), "r"(a1), "r"(a2), "r"(a3), "r"(b0), "r"(b1));
}
// bf16 packing (attention P-split): {lo16 = a.hi16, hi16 = b.hi16}
__device__ __forceinline__ uint32_t prmt_hi(float a, float b) {
    uint32_t d;
    asm("prmt.b32 %0, %1, %2, 0x7632;" : "=r"(d) : "r"(__float_as_uint(a)), "r"(__float_as_uint(b)));
    return d;
}
__device__ __forceinline__ uint32_t packbf(float lo, float hi) {
    uint32_t d;
    asm("cvt.rn.bf16x2.f32 %0, %1, %2;" : "=r"(d) : "f"(hi), "f"(lo));
    return d;
}
__device__ __forceinline__ float truncbf(float v) {
    return __uint_as_float(__float_as_uint(v) & 0xFFFF0000u);
}

// ============================================================================
// Conversions.  dsel 0: x -> fp16 hi/lo split.  dsel 1..4: W -> fp16.
// ============================================================================
__global__ __launch_bounds__(256) void split_kernel(const float* __restrict__ src,
                                                    int dsel, int n4) {
    int i = blockIdx.x * 256 + threadIdx.x;
    if (i >= n4) return;
    float4 v = ((const float4*)src)[i];
    __half h0 = __float2half_rn(v.x), h1 = __float2half_rn(v.y);
    __half h2 = __float2half_rn(v.z), h3 = __float2half_rn(v.w);
    if (dsel == 0) {
        __half l0 = __float2half_rn(v.x - __half2float(h0));
        __half l1 = __float2half_rn(v.y - __half2float(h1));
        __half l2 = __float2half_rn(v.z - __half2float(h2));
        __half l3 = __float2half_rn(v.w - __half2float(h3));
        __half2* H = (__half2*)g_xhi;  __half2* L = (__half2*)g_xlo;
        H[2*i]   = __halves2half2(h0, h1);  H[2*i+1] = __halves2half2(h2, h3);
        L[2*i]   = __halves2half2(l0, l1);  L[2*i+1] = __halves2half2(l2, l3);
    } else {
        __half2* H = (__half2*)g_wh[dsel-1];
        H[2*i]   = __halves2half2(h0, h1);  H[2*i+1] = __halves2half2(h2, h3);
    }
}

// ============================================================================
// 2-pass split-fp16 GEMM: C = (Ahi+Alo) @ W~^T + bias
// 128x128 tile, BK=32, 3 smem tiles/stage (Ahi, Alo, W), 3-stage pipeline.
// fused=1: QKV in one launch, w_idx = blockIdx.x>>3, scatter to split-bf16 QKV.
// fused=0: O projection, fp32 out.
// ============================================================================
#define RS    40
#define GTB   (128*RS*2)          // 10240 bytes per tile
#define GSTG  (3*GTB)             // 30720 per stage
#define GSMEM (3*GSTG)            // 92160
#define GNIT  32

__global__ __launch_bounds__(256) void gemm_hmma(
    const float* __restrict__ b0, const float* __restrict__ b1,
    const float* __restrict__ b2, float* __restrict__ out_ext,
    int a_sel, int fused)
{
    extern __shared__ char smc[];
    uint32_t smbase = smem_u32(smc);
    int tid = threadIdx.x, lane = tid & 31, wid = tid >> 5;
    int mb = blockIdx.y * 128;
    int w_idx, nb, dst_sel;
    const float* bias;
    if (fused) {
        w_idx = blockIdx.x >> 3;  nb = (blockIdx.x & 7) * 128;  dst_sel = w_idx;
        bias = (w_idx == 0) ? b0 : (w_idx == 1) ? b1 : b2;
    } else {
        w_idx = 3;  nb = blockIdx.x * 128;  dst_sel = 3;  bias = b0;
    }
    int wm = (wid >> 2) * 64, wn = (wid & 3) * 32;

    const __half* Ahi = a_sel ? g_ahi : g_xhi;
    const __half* Alo = a_sel ? g_alo : g_xlo;
    const __half* Bw  = g_wh[w_idx];

    int r0c = tid >> 2;                  // 0..63
    int r1c = r0c + 64;                  // 64..127
    int cc0 = (tid & 3) * 8;

    float acc[4][4][4];
    #pragma unroll
    for (int i = 0; i < 4; i++)
        #pragma unroll
        for (int j = 0; j < 4; j++)
            #pragma unroll
            for (int r = 0; r < 4; r++) acc[i][j][r] = 0.f;

    auto stage = [&](int kidx) {
        int kk = kidx * 32;
        uint32_t buf = smbase + (kidx % 3) * GSTG;
        const __half* p0 = Ahi + (size_t)mb * EMB + kk;
        const __half* p1 = Alo + (size_t)mb * EMB + kk;
        const __half* p2 = Bw  + (size_t)nb * EMB + kk;
        CP16(buf + 0*GTB + (r0c*RS + cc0)*2, p0 + (size_t)r0c*EMB + cc0);
        CP16(buf + 0*GTB + (r1c*RS + cc0)*2, p0 + (size_t)r1c*EMB + cc0);
        CP16(buf + 1*GTB + (r0c*RS + cc0)*2, p1 + (size_t)r0c*EMB + cc0);
        CP16(buf + 1*GTB + (r1c*RS + cc0)*2, p1 + (size_t)r1c*EMB + cc0);
        CP16(buf + 2*GTB + (r0c*RS + cc0)*2, p2 + (size_t)r0c*EMB + cc0);
        CP16(buf + 2*GTB + (r1c*RS + cc0)*2, p2 + (size_t)r1c*EMB + cc0);
        CP_COMMIT();
    };

    stage(0); stage(1);

    int a_row = wm + (lane & 15);
    int a_half = (lane & 16) ? 8 : 0;
    int b_row = wn + (lane & 7) + ((lane & 16) ? 8 : 0);
    int b_half = (lane & 8) ? 8 : 0;

    for (int i = 0; i < GNIT; i++) {
        if (i == GNIT-1) CP_WAIT0(); else CP_WAIT1();
        __syncthreads();
        if (i + 2 < GNIT) stage(i + 2);

        uint32_t buf = smbase + (i % 3) * GSTG;
        #pragma unroll
        for (int ks = 0; ks < 2; ks++) {
            uint32_t ah[4][4], al[4][4], bh[2][4];
            #pragma unroll
            for (int mi = 0; mi < 4; mi++) {
                uint32_t off = ((a_row + mi*16)*RS + ks*16 + a_half)*2;
                ldsm4(buf + 0*GTB + off, ah[mi]);
                ldsm4(buf + 1*GTB + off, al[mi]);
            }
            #pragma unroll
            for (int np = 0; np < 2; np++) {
                uint32_t off = ((b_row + np*16)*RS + ks*16 + b_half)*2;
                ldsm4(buf + 2*GTB + off, bh[np]);
            }
            #pragma unroll
            for (int mi = 0; mi < 4; mi++)
                #pragma unroll
                for (int nj = 0; nj < 4; nj++) {
                    uint32_t q0 = bh[nj>>1][(nj&1)*2], q1 = bh[nj>>1][(nj&1)*2+1];
                    mma_f16(acc[mi][nj], ah[mi][0], ah[mi][1], ah[mi][2], ah[mi][3], q0, q1);
                    mma_f16(acc[mi][nj], al[mi][0], al[mi][1], al[mi][2], al[mi][3], q0, q1);
                }
        }
    }

    // Epilogue
    #pragma unroll
    for (int mi = 0; mi < 4; mi++) {
        #pragma unroll
        for (int nj = 0; nj < 4; nj++) {
            int row = mb + wm + mi*16 + (lane >> 2);
            int col = nb + wn + nj*8 + 2*(lane & 3);
            float2 bv = *(const float2*)(bias + col);
            #pragma unroll
            for (int half = 0; half < 2; half++) {
                int rr = row + half*8;
                float v0 = acc[mi][nj][2*half+0] + bv.x;
                float v1 = acc[mi][nj][2*half+1] + bv.y;
                if (dst_sel == 3) {
                    *(float2*)(out_ext + (size_t)rr * EMB + col) = make_float2(v0, v1);
                    continue;
                }
                int bb = rr >> 11, tt = rr & 2047;
                int hh = col >> 6, d0 = col & 63;
                if (dst_sel == 0) { v0 *= SCALE; v1 *= SCALE; }
                __nv_bfloat16 h0 = __float2bfloat16(v0), h1 = __float2bfloat16(v1);
                __nv_bfloat16 l0 = __float2bfloat16(v0 - __bfloat162float(h0));
                __nv_bfloat16 l1 = __float2bfloat16(v1 - __bfloat162float(h1));
                if (dst_sel == 2) {
                    size_t base = ((size_t)(bb*NH + hh) * HD + d0) * SEQ + tt;
                    g_vthi[base] = h0;  g_vthi[base + SEQ] = h1;
                    g_vtlo[base] = l0;  g_vtlo[base + SEQ] = l1;
                } else {
                    size_t base = ((size_t)(bb*NH + hh) * SEQ + tt) * HD + d0;
                    __nv_bfloat16* Hd = dst_sel ? g_khi : g_qhi;
                    __nv_bfloat16* Ld = dst_sel ? g_klo : g_qlo;
                    *(__nv_bfloat162*)(Hd + base) = __nv_bfloat162(h0, h1);
                    *(__nv_bfloat162*)(Ld + base) = __nv_bfloat162(l0, l1);
                }
            }
        }
    }
}

// ============================================================================
// Tensor-core attention (round-5, known-good), epilogue now writes fp16 split.
// ============================================================================
#define QT   64
#define KT   64
#define RSA  72
#define AQB  (64*RSA*2)
#define ASTG (4*AQB)
#define ASMEM (2*AQB + 2*ASTG)

__global__ __launch_bounds__(128) void attn_tc()
{
    extern __shared__ char smc[];
    uint32_t sb = smem_u32(smc);
    int tid = threadIdx.x, lane = tid & 31, wid = tid >> 5;
    int bh = blockIdx.y, h = bh & (NH-1), bb = bh >> 4;
    int q0 = blockIdx.x * QT;

    const __nv_bfloat16* Qhp = g_qhi + ((size_t)bh*SEQ + q0) * HD;
    const __nv_bfloat16* Qlp = g_qlo + ((size_t)bh*SEQ + q0) * HD;
    const __nv_bfloat16* Khp = g_khi + (size_t)bh*SEQ*HD;
    const __nv_bfloat16* Klp = g_klo + (size_t)bh*SEQ*HD;
    const __nv_bfloat16* Vhp = g_vthi + (size_t)bh*SEQ*HD;
    const __nv_bfloat16* Vlp = g_vtlo + (size_t)bh*SEQ*HD;

    int kt0, kt1;
    if (h == 0) { kt0 = 0; kt1 = SEQ / KT; }
    else {
        int lo = q0 - LOCALK; if (lo < 0) lo = 0;
        int hi = q0 + QT + LOCALK; if (hi > SEQ) hi = SEQ;
        kt0 = lo / KT; kt1 = hi / KT;
    }
    int nkt = kt1 - kt0;

    auto stage_kv = [&](int buf, int ktile) {
        uint32_t stg = sb + 2*AQB + buf*ASTG;
        int k0 = ktile * KT;
        #pragma unroll
        for (int j = 0; j < 4; j++) {
            int idx = tid + j*128;
            int r = idx >> 3, c = (idx & 7) * 8;
            uint32_t off = (uint32_t)(r*RSA + c) * 2;
            CP16(stg + 0*AQB + off, Khp + (size_t)(k0 + r)*HD + c);
            CP16(stg + 1*AQB + off, Klp + (size_t)(k0 + r)*HD + c);
            CP16(stg + 2*AQB + off, Vhp + (size_t)r*SEQ + k0 + c);
            CP16(stg + 3*AQB + off, Vlp + (size_t)r*SEQ + k0 + c);
        }
    };

    #pragma unroll
    for (int j = 0; j < 4; j++) {
        int idx = tid + j*128;
        int r = idx >> 3, c = (idx & 7) * 8;
        uint32_t off = (uint32_t)(r*RSA + c) * 2;
        CP16(sb + 0   + off, Qhp + (size_t)r*HD + c);
        CP16(sb + AQB + off, Qlp + (size_t)r*HD + c);
    }
    stage_kv(0, kt0);
    CP_COMMIT();

    uint32_t a_off = (uint32_t)((wid*16 + (lane & 15))*RSA + ((lane & 16) ? 8 : 0)) * 2;
    int b_row = (lane & 7) + ((lane & 16) ? 8 : 0);
    int b_half = (lane & 8) ? 8 : 0;
    int r0g = q0 + wid*16 + (lane >> 2);

    float o[8][4];
    #pragma unroll
    for (int nj = 0; nj < 8; nj++)
        #pragma unroll
        for (int r = 0; r < 4; r++) o[nj][r] = 0.f;
    float m0 = NEGF, m1 = NEGF, l0 = 0.f, l1 = 0.f;
    uint32_t qh[4][4], ql[4][4];

    for (int it = 0; it < nkt; it++) {
        uint32_t stg = sb + 2*AQB + (it & 1)*ASTG;
        if (it + 1 < nkt) { stage_kv((it+1) & 1, kt0 + it + 1); CP_COMMIT(); CP_WAIT1(); }
        else CP_WAIT0();
        __syncthreads();

        if (it == 0) {
            #pragma unroll
            for (int ks = 0; ks < 4; ks++) {
                ldsm4(sb + 0   + a_off + ks*32, qh[ks]);
                ldsm4(sb + AQB + a_off + ks*32, ql[ks]);
            }
        }

        float s[8][4];
        #pragma unroll
        for (int nj = 0; nj < 8; nj++)
            #pragma unroll
            for (int r = 0; r < 4; r++) s[nj][r] = 0.f;

        #pragma unroll
        for (int ks = 0; ks < 4; ks++) {
            uint32_t b[4][4];
            #pragma unroll
            for (int np = 0; np < 4; np++)
                ldsm4(stg + 0*AQB + ((b_row + np*16)*RSA + ks*16 + b_half)*2, b[np]);
            #pragma unroll
            for (int nj = 0; nj < 8; nj++) {
                uint32_t q0r = b[nj>>1][(nj&1)*2], q1r = b[nj>>1][(nj&1)*2+1];
                mma_bf16(s[nj], qh[ks][0], qh[ks][1], qh[ks][2], qh[ks][3], q0r, q1r);
                mma_bf16(s[nj], ql[ks][0], ql[ks][1], ql[ks][2], ql[ks][3], q0r, q1r);
            }
        }
        #pragma unroll
        for (int ks = 0; ks < 4; ks++) {
            uint32_t b[4][4];
            #pragma unroll
            for (int np = 0; np < 4; np++)
                ldsm4(stg + 1*AQB + ((b_row + np*16)*RSA + ks*16 + b_half)*2, b[np]);
            #pragma unroll
            for (int nj = 0; nj < 8; nj++)
                mma_bf16(s[nj], qh[ks][0], qh[ks][1], qh[ks][2], qh[ks][3],
                         b[nj>>1][(nj&1)*2], b[nj>>1][(nj&1)*2+1]);
        }

        int k0 = (kt0 + it) * KT;
        if (h != 0) {
            #pragma unroll
            for (int nj = 0; nj < 8; nj++) {
                int c0 = k0 + nj*8 + 2*(lane & 3);
                if (abs(r0g - c0)     > LOCALK) s[nj][0] = NEGF;
                if (abs(r0g - c0 - 1) > LOCALK) s[nj][1] = NEGF;
                if (abs(r0g + 8 - c0)     > LOCALK) s[nj][2] = NEGF;
                if (abs(r0g + 8 - c0 - 1) > LOCALK) s[nj][3] = NEGF;
            }
        }

        float mx0 = NEGF, mx1 = NEGF;
        #pragma unroll
        for (int nj = 0; nj < 8; nj++) {
            mx0 = fmaxf(mx0, fmaxf(s[nj][0], s[nj][1]));
            mx1 = fmaxf(mx1, fmaxf(s[nj][2], s[nj][3]));
        }
        mx0 = fmaxf(mx0, __shfl_xor_sync(0xffffffffu, mx0, 1));
        mx0 = fmaxf(mx0, __shfl_xor_sync(0xffffffffu, mx0, 2));
        mx1 = fmaxf(mx1, __shfl_xor_sync(0xffffffffu, mx1, 1));
        mx1 = fmaxf(mx1, __shfl_xor_sync(0xffffffffu, mx1, 2));
        float nm0 = fmaxf(m0, mx0), nm1 = fmaxf(m1, mx1);
        float cr0 = __expf(m0 - nm0), cr1 = __expf(m1 - nm1);
        m0 = nm0; m1 = nm1; l0 *= cr0; l1 *= cr1;
        #pragma unroll
        for (int nj = 0; nj < 8; nj++) {
            o[nj][0] *= cr0; o[nj][1] *= cr0;
            o[nj][2] *= cr1; o[nj][3] *= cr1;
        }
        float rs0 = 0.f, rs1 = 0.f;
        #pragma unroll
        for (int nj = 0; nj < 8; nj++) {
            float p0 = __expf(s[nj][0] - m0), p1 = __expf(s[nj][1] - m0);
            float p2 = __expf(s[nj][2] - m1), p3 = __expf(s[nj][3] - m1);
            rs0 += p0 + p1; rs1 += p2 + p3;
            uint32_t h01 = prmt_hi(p0, p1), h23 = prmt_hi(p2, p3);
            uint32_t lo01 = packbf(p0 - truncbf(p0), p1 - truncbf(p1));
            uint32_t lo23 = packbf(p2 - truncbf(p2), p3 - truncbf(p3));
            s[nj][0] = __uint_as_float(h01);  s[nj][1] = __uint_as_float(h23);
            s[nj][2] = __uint_as_float(lo01); s[nj][3] = __uint_as_float(lo23);
        }
        rs0 += __shfl_xor_sync(0xffffffffu, rs0, 1);
        rs0 += __shfl_xor_sync(0xffffffffu, rs0, 2);
        rs1 += __shfl_xor_sync(0xffffffffu, rs1, 1);
        rs1 += __shfl_xor_sync(0xffffffffu, rs1, 2);
        l0 += rs0; l1 += rs1;

        #pragma unroll
        for (int kc = 0; kc < 4; kc++) {
            uint32_t ah0 = __float_as_uint(s[2*kc][0]),   ah1 = __float_as_uint(s[2*kc][1]);
            uint32_t ah2 = __float_as_uint(s[2*kc+1][0]), ah3 = __float_as_uint(s[2*kc+1][1]);
            uint32_t al0 = __float_as_uint(s[2*kc][2]),   al1 = __float_as_uint(s[2*kc][3]);
            uint32_t al2 = __float_as_uint(s[2*kc+1][2]), al3 = __float_as_uint(s[2*kc+1][3]);
            uint32_t b[4][4];
            #pragma unroll
            for (int np = 0; np < 4; np++)
                ldsm4(stg + 2*AQB + ((b_row + np*16)*RSA + kc*16 + b_half)*2, b[np]);
            #pragma unroll
            for (int nj = 0; nj < 8; nj++) {
                uint32_t q0r = b[nj>>1][(nj&1)*2], q1r = b[nj>>1][(nj&1)*2+1];
                mma_bf16(o[nj], ah0, ah1, ah2, ah3, q0r, q1r);
                mma_bf16(o[nj], al0, al1, al2, al3, q0r, q1r);
            }
            #pragma unroll
            for (int np = 0; np < 4; np++)
                ldsm4(stg + 3*AQB + ((b_row + np*16)*RSA + kc*16 + b_half)*2, b[np]);
            #pragma unroll
            for (int nj = 0; nj < 8; nj++)
                mma_bf16(o[nj], ah0, ah1, ah2, ah3,
                         b[nj>>1][(nj&1)*2], b[nj>>1][(nj&1)*2+1]);
        }
        __syncthreads();
    }

    // Epilogue: normalize, fp16 split, store
    float inv0 = 1.f / l0, inv1 = 1.f / l1;
    #pragma unroll
    for (int nj = 0; nj < 8; nj++) {
        int d = nj*8 + 2*(lane & 3);
        float v0 = o[nj][0]*inv0, v1 = o[nj][1]*inv0;
        float v2 = o[nj][2]*inv1, v3 = o[nj][3]*inv1;
        __half h0 = __float2half_rn(v0), h1 = __float2half_rn(v1);
        __half h2 = __float2half_rn(v2), h3 = __float2half_rn(v3);
        __half r0 = __float2half_rn(v0 - __half2float(h0));
        __half r1 = __float2half_rn(v1 - __half2float(h1));
        __half r2 = __float2half_rn(v2 - __half2float(h2));
        __half r3 = __float2half_rn(v3 - __half2float(h3));
        size_t base0 = ((size_t)(bb*SEQ + r0g)) * EMB + h*HD + d;
        size_t base1 = ((size_t)(bb*SEQ + r0g + 8)) * EMB + h*HD + d;
        *(__half2*)(g_ahi + base0) = __halves2half2(h0, h1);
        *(__half2*)(g_alo + base0) = __halves2half2(r0, r1);
        *(__half2*)(g_ahi + base1) = __halves2half2(h2, h3);
        *(__half2*)(g_alo + base1) = __halves2half2(r2, r3);
    }
}

// ============================================================================
// Launch
// ============================================================================
extern "C" void kernel_launch(void* const* d_in, const int* in_sizes, int n_in,
                              void* d_out, int out_size)
{
    (void)in_sizes; (void)n_in; (void)out_size;
    const float* x  = (const float*)d_in[0];
    const float* wq = (const float*)d_in[1];
    const float* bq = (const float*)d_in[2];
    const float* wk = (const float*)d_in[3];
    const float* bk = (const float*)d_in[4];
    const float* wv = (const float*)d_in[5];
    const float* bv = (const float*)d_in[6];
    const float* wo = (const float*)d_in[7];
    const float* bo = (const float*)d_in[8];
    float* out = (float*)d_out;

    cudaFuncSetAttribute(gemm_hmma, cudaFuncAttributeMaxDynamicSharedMemorySize, GSMEM);
    cudaFuncSetAttribute(attn_tc,   cudaFuncAttributeMaxDynamicSharedMemorySize, ASMEM);

    split_kernel<<<SZ/4/256, 256>>>(x,  0, SZ/4);
    split_kernel<<<EMB*EMB/4/256, 256>>>(wq, 1, EMB*EMB/4);
    split_kernel<<<EMB*EMB/4/256, 256>>>(wk, 2, EMB*EMB/4);
    split_kernel<<<EMB*EMB/4/256, 256>>>(wv, 3, EMB*EMB/4);
    split_kernel<<<EMB*EMB/4/256, 256>>>(wo, 4, EMB*EMB/4);

    // Fused QKV: grid.x = 3 weights x 8 N-tiles
    gemm_hmma<<<dim3(24, 64), 256, GSMEM>>>(bq, bk, bv, nullptr, 0, 1);

    attn_tc<<<dim3(SEQ/QT, B_*NH), 128, ASMEM>>>();

    // O projection
    gemm_hmma<<<dim3(8, 64), 256, GSMEM>>>(bo, nullptr, nullptr, out, 1, 0);
}

// round 7
// speedup vs baseline: 4.2569x; 1.0031x over previous
#include <cuda_runtime.h>
#include <cuda_bf16.h>
#include <cuda_fp16.h>
#include <cstdint>
#include <math.h>

// Problem constants
#define B_   4
#define SEQ  2048
#define EMB  1024
#define NH   16
#define HD   64
#define SZ   (B_*SEQ*EMB)     // 8,388,608
#define LOCALK 128
#define SCALE  0.125f
#define NEGF  (-1e30f)

// Scratch
__device__ __align__(16) __half g_xhi[SZ], g_xlo[SZ];            // x split (fp16)
__device__ __align__(16) __half g_ahi[SZ], g_alo[SZ];            // attn out split (fp16)
__device__ __align__(16) __half g_wh[4][EMB*EMB];                // weights (fp16)
__device__ __align__(16) __nv_bfloat16 g_qhi[SZ], g_qlo[SZ];     // [bh][t][d], pre-scaled
__device__ __align__(16) __nv_bfloat16 g_khi[SZ], g_klo[SZ];     // [bh][t][d]
__device__ __align__(16) __nv_bfloat16 g_vthi[SZ], g_vtlo[SZ];   // [bh][d][t]

// ============================================================================
// Helpers
// ============================================================================
__device__ __forceinline__ uint32_t smem_u32(const void* p) {
    uint32_t a;
    asm("{ .reg .u64 t; cvta.to.shared.u64 t, %1; cvt.u32.u64 %0, t; }" : "=r"(a) : "l"(p));
    return a;
}
#define CP16(dst, src) asm volatile("cp.async.cg.shared.global [%0], [%1], 16;" :: "r"(dst), "l"(src))
#define CP_COMMIT()    asm volatile("cp.async.commit_group;" ::: "memory")
#define CP_WAIT1()     asm volatile("cp.async.wait_group 1;" ::: "memory")
#define CP_WAIT0()     asm volatile("cp.async.wait_group 0;" ::: "memory")

__device__ __forceinline__ void ldsm4(uint32_t addr, uint32_t* r) {
    asm volatile("ldmatrix.sync.aligned.m8n8.x4.shared.b16 {%0,%1,%2,%3}, [%4];"
                 : "=r"(r[0]), "=r"(r[1]), "=r"(r[2]), "=r"(r[3]) : "r"(addr));
}
__device__ __forceinline__ void mma_bf16(float* c, uint32_t a0, uint32_t a1, uint32_t a2,
                                         uint32_t a3, uint32_t b0, uint32_t b1) {
    asm volatile(
        "mma.sync.aligned.m16n8k16.row.col.f32.bf16.bf16.f32 "
        "{%0,%1,%2,%3}, {%4,%5,%6,%7}, {%8,%9}, {%0,%1,%2,%3};"
        : "+f"(c[0]), "+f"(c[1]), "+f"(c[2]), "+f"(c[3])
        : "r"(a0), "r"(a1), "r"(a2), "r"(a3), "r"(b0), "r"(b1));
}
__device__ __forceinline__ void mma_f16(float* c, uint32_t a0, uint32_t a1, uint32_t a2,
                                        uint32_t a3, uint32_t b0, uint32_t b1) {
    asm volatile(
        "mma.sync.aligned.m16n8k16.row.col.f32.f16.f16.f32 "
        "{%0,%1,%2,%3}, {%4,%5,%6,%7}, {%8,%9}, {%0,%1,%2,%3};"
        : "+f"(c[0]), "+f"(c[1]), "+f"(c[2]), "+f"(c[3])
        : "r"(a0), "r"(a1), "r"(a2), "r"(a3), "r"(b0), "r"(b1));
}
// bf16 packing (attention P-split): {lo16 = a.hi16, hi16 = b.hi16}
__device__ __forceinline__ uint32_t prmt_hi(float a, float b) {
    uint32_t d;
    asm("prmt.b32 %0, %1, %2, 0x7632;" : "=r"(d) : "r"(__float_as_uint(a)), "r"(__float_as_uint(b)));
    return d;
}
__device__ __forceinline__ uint32_t packbf(float lo, float hi) {
    uint32_t d;
    asm("cvt.rn.bf16x2.f32 %0, %1, %2;" : "=r"(d) : "f"(hi), "f"(lo));
    return d;
}
__device__ __forceinline__ float truncbf(float v) {
    return __uint_as_float(__float_as_uint(v) & 0xFFFF0000u);
}

// ============================================================================
// Conversions.  dsel 0: x -> fp16 hi/lo split.  dsel 1..4: W -> fp16.
// ============================================================================
__global__ __launch_bounds__(256) void split_kernel(const float* __restrict__ src,
                                                    int dsel, int n4) {
    int i = blockIdx.x * 256 + threadIdx.x;
    if (i >= n4) return;
    float4 v = ((const float4*)src)[i];
    __half h0 = __float2half_rn(v.x), h1 = __float2half_rn(v.y);
    __half h2 = __float2half_rn(v.z), h3 = __float2half_rn(v.w);
    if (dsel == 0) {
        __half l0 = __float2half_rn(v.x - __half2float(h0));
        __half l1 = __float2half_rn(v.y - __half2float(h1));
        __half l2 = __float2half_rn(v.z - __half2float(h2));
        __half l3 = __float2half_rn(v.w - __half2float(h3));
        __half2* H = (__half2*)g_xhi;  __half2* L = (__half2*)g_xlo;
        H[2*i]   = __halves2half2(h0, h1);  H[2*i+1] = __halves2half2(h2, h3);
        L[2*i]   = __halves2half2(l0, l1);  L[2*i+1] = __halves2half2(l2, l3);
    } else {
        __half2* H = (__half2*)g_wh[dsel-1];
        H[2*i]   = __halves2half2(h0, h1);  H[2*i+1] = __halves2half2(h2, h3);
    }
}

// ============================================================================
// 2-pass split-fp16 GEMM: C = (Ahi+Alo) @ W~^T + bias
// 128x128 tile, BK=32, 3 smem tiles/stage (Ahi, Alo, W), 3-stage pipeline.
// fused=1: QKV in one launch, w_idx = blockIdx.x>>3, scatter to split-bf16 QKV.
// fused=0: O projection, fp32 out.
// ============================================================================
#define RS    40
#define GTB   (128*RS*2)          // 10240 bytes per tile
#define GSTG  (3*GTB)             // 30720 per stage
#define GSMEM (3*GSTG)            // 92160
#define GNIT  32

__global__ __launch_bounds__(256) void gemm_hmma(
    const float* __restrict__ b0, const float* __restrict__ b1,
    const float* __restrict__ b2, float* __restrict__ out_ext,
    int a_sel, int fused)
{
    extern __shared__ char smc[];
    uint32_t smbase = smem_u32(smc);
    int tid = threadIdx.x, lane = tid & 31, wid = tid >> 5;
    int mb = blockIdx.y * 128;
    int w_idx, nb, dst_sel;
    const float* bias;
    if (fused) {
        w_idx = blockIdx.x >> 3;  nb = (blockIdx.x & 7) * 128;  dst_sel = w_idx;
        bias = (w_idx == 0) ? b0 : (w_idx == 1) ? b1 : b2;
    } else {
        w_idx = 3;  nb = blockIdx.x * 128;  dst_sel = 3;  bias = b0;
    }
    int wm = (wid >> 2) * 64, wn = (wid & 3) * 32;

    const __half* Ahi = a_sel ? g_ahi : g_xhi;
    const __half* Alo = a_sel ? g_alo : g_xlo;
    const __half* Bw  = g_wh[w_idx];

    int r0c = tid >> 2;                  // 0..63
    int r1c = r0c + 64;                  // 64..127
    int cc0 = (tid & 3) * 8;

    float acc[4][4][4];
    #pragma unroll
    for (int i = 0; i < 4; i++)
        #pragma unroll
        for (int j = 0; j < 4; j++)
            #pragma unroll
            for (int r = 0; r < 4; r++) acc[i][j][r] = 0.f;

    auto stage = [&](int kidx) {
        int kk = kidx * 32;
        uint32_t buf = smbase + (kidx % 3) * GSTG;
        const __half* p0 = Ahi + (size_t)mb * EMB + kk;
        const __half* p1 = Alo + (size_t)mb * EMB + kk;
        const __half* p2 = Bw  + (size_t)nb * EMB + kk;
        CP16(buf + 0*GTB + (r0c*RS + cc0)*2, p0 + (size_t)r0c*EMB + cc0);
        CP16(buf + 0*GTB + (r1c*RS + cc0)*2, p0 + (size_t)r1c*EMB + cc0);
        CP16(buf + 1*GTB + (r0c*RS + cc0)*2, p1 + (size_t)r0c*EMB + cc0);
        CP16(buf + 1*GTB + (r1c*RS + cc0)*2, p1 + (size_t)r1c*EMB + cc0);
        CP16(buf + 2*GTB + (r0c*RS + cc0)*2, p2 + (size_t)r0c*EMB + cc0);
        CP16(buf + 2*GTB + (r1c*RS + cc0)*2, p2 + (size_t)r1c*EMB + cc0);
        CP_COMMIT();
    };

    stage(0); stage(1);

    int a_row = wm + (lane & 15);
    int a_half = (lane & 16) ? 8 : 0;
    int b_row = wn + (lane & 7) + ((lane & 16) ? 8 : 0);
    int b_half = (lane & 8) ? 8 : 0;

    for (int i = 0; i < GNIT; i++) {
        if (i == GNIT-1) CP_WAIT0(); else CP_WAIT1();
        __syncthreads();
        if (i + 2 < GNIT) stage(i + 2);

        uint32_t buf = smbase + (i % 3) * GSTG;
        #pragma unroll
        for (int ks = 0; ks < 2; ks++) {
            uint32_t ah[4][4], al[4][4], bh[2][4];
            #pragma unroll
            for (int mi = 0; mi < 4; mi++) {
                uint32_t off = ((a_row + mi*16)*RS + ks*16 + a_half)*2;
                ldsm4(buf + 0*GTB + off, ah[mi]);
                ldsm4(buf + 1*GTB + off, al[mi]);
            }
            #pragma unroll
            for (int np = 0; np < 2; np++) {
                uint32_t off = ((b_row + np*16)*RS + ks*16 + b_half)*2;
                ldsm4(buf + 2*GTB + off, bh[np]);
            }
            #pragma unroll
            for (int mi = 0; mi < 4; mi++)
                #pragma unroll
                for (int nj = 0; nj < 4; nj++) {
                    uint32_t q0 = bh[nj>>1][(nj&1)*2], q1 = bh[nj>>1][(nj&1)*2+1];
                    mma_f16(acc[mi][nj], ah[mi][0], ah[mi][1], ah[mi][2], ah[mi][3], q0, q1);
                    mma_f16(acc[mi][nj], al[mi][0], al[mi][1], al[mi][2], al[mi][3], q0, q1);
                }
        }
    }

    // Epilogue
    #pragma unroll
    for (int mi = 0; mi < 4; mi++) {
        #pragma unroll
        for (int nj = 0; nj < 4; nj++) {
            int row = mb + wm + mi*16 + (lane >> 2);
            int col = nb + wn + nj*8 + 2*(lane & 3);
            float2 bv = *(const float2*)(bias + col);
            #pragma unroll
            for (int half = 0; half < 2; half++) {
                int rr = row + half*8;
                float v0 = acc[mi][nj][2*half+0] + bv.x;
                float v1 = acc[mi][nj][2*half+1] + bv.y;
                if (dst_sel == 3) {
                    *(float2*)(out_ext + (size_t)rr * EMB + col) = make_float2(v0, v1);
                    continue;
                }
                int bb = rr >> 11, tt = rr & 2047;
                int hh = col >> 6, d0 = col & 63;
                if (dst_sel == 0) { v0 *= SCALE; v1 *= SCALE; }
                __nv_bfloat16 h0 = __float2bfloat16(v0), h1 = __float2bfloat16(v1);
                __nv_bfloat16 l0 = __float2bfloat16(v0 - __bfloat162float(h0));
                __nv_bfloat16 l1 = __float2bfloat16(v1 - __bfloat162float(h1));
                if (dst_sel == 2) {
                    size_t base = ((size_t)(bb*NH + hh) * HD + d0) * SEQ + tt;
                    g_vthi[base] = h0;  g_vthi[base + SEQ] = h1;
                    g_vtlo[base] = l0;  g_vtlo[base + SEQ] = l1;
                } else {
                    size_t base = ((size_t)(bb*NH + hh) * SEQ + tt) * HD + d0;
                    __nv_bfloat16* Hd = dst_sel ? g_khi : g_qhi;
                    __nv_bfloat16* Ld = dst_sel ? g_klo : g_qlo;
                    *(__nv_bfloat162*)(Hd + base) = __nv_bfloat162(h0, h1);
                    *(__nv_bfloat162*)(Ld + base) = __nv_bfloat162(l0, l1);
                }
            }
        }
    }
}

// ============================================================================
// Tensor-core attention (round-5, known-good), epilogue now writes fp16 split.
// ============================================================================
#define QT   64
#define KT   64
#define RSA  72
#define AQB  (64*RSA*2)
#define ASTG (4*AQB)
#define ASMEM (2*AQB + 2*ASTG)

__global__ __launch_bounds__(128) void attn_tc()
{
    extern __shared__ char smc[];
    uint32_t sb = smem_u32(smc);
    int tid = threadIdx.x, lane = tid & 31, wid = tid >> 5;
    int bh = blockIdx.y, h = bh & (NH-1), bb = bh >> 4;
    int q0 = blockIdx.x * QT;

    const __nv_bfloat16* Qhp = g_qhi + ((size_t)bh*SEQ + q0) * HD;
    const __nv_bfloat16* Qlp = g_qlo + ((size_t)bh*SEQ + q0) * HD;
    const __nv_bfloat16* Khp = g_khi + (size_t)bh*SEQ*HD;
    const __nv_bfloat16* Klp = g_klo + (size_t)bh*SEQ*HD;
    const __nv_bfloat16* Vhp = g_vthi + (size_t)bh*SEQ*HD;
    const __nv_bfloat16* Vlp = g_vtlo + (size_t)bh*SEQ*HD;

    int kt0, kt1;
    if (h == 0) { kt0 = 0; kt1 = SEQ / KT; }
    else {
        int lo = q0 - LOCALK; if (lo < 0) lo = 0;
        int hi = q0 + QT + LOCALK; if (hi > SEQ) hi = SEQ;
        kt0 = lo / KT; kt1 = hi / KT;
    }
    int nkt = kt1 - kt0;

    auto stage_kv = [&](int buf, int ktile) {
        uint32_t stg = sb + 2*AQB + buf*ASTG;
        int k0 = ktile * KT;
        #pragma unroll
        for (int j = 0; j < 4; j++) {
            int idx = tid + j*128;
            int r = idx >> 3, c = (idx & 7) * 8;
            uint32_t off = (uint32_t)(r*RSA + c) * 2;
            CP16(stg + 0*AQB + off, Khp + (size_t)(k0 + r)*HD + c);
            CP16(stg + 1*AQB + off, Klp + (size_t)(k0 + r)*HD + c);
            CP16(stg + 2*AQB + off, Vhp + (size_t)r*SEQ + k0 + c);
            CP16(stg + 3*AQB + off, Vlp + (size_t)r*SEQ + k0 + c);
        }
    };

    #pragma unroll
    for (int j = 0; j < 4; j++) {
        int idx = tid + j*128;
        int r = idx >> 3, c = (idx & 7) * 8;
        uint32_t off = (uint32_t)(r*RSA + c) * 2;
        CP16(sb + 0   + off, Qhp + (size_t)r*HD + c);
        CP16(sb + AQB + off, Qlp + (size_t)r*HD + c);
    }
    stage_kv(0, kt0);
    CP_COMMIT();

    uint32_t a_off = (uint32_t)((wid*16 + (lane & 15))*RSA + ((lane & 16) ? 8 : 0)) * 2;
    int b_row = (lane & 7) + ((lane & 16) ? 8 : 0);
    int b_half = (lane & 8) ? 8 : 0;
    int r0g = q0 + wid*16 + (lane >> 2);

    float o[8][4];
    #pragma unroll
    for (int nj = 0; nj < 8; nj++)
        #pragma unroll
        for (int r = 0; r < 4; r++) o[nj][r] = 0.f;
    float m0 = NEGF, m1 = NEGF, l0 = 0.f, l1 = 0.f;
    uint32_t qh[4][4], ql[4][4];

    for (int it = 0; it < nkt; it++) {
        uint32_t stg = sb + 2*AQB + (it & 1)*ASTG;
        if (it + 1 < nkt) { stage_kv((it+1) & 1, kt0 + it + 1); CP_COMMIT(); CP_WAIT1(); }
        else CP_WAIT0();
        __syncthreads();

        if (it == 0) {
            #pragma unroll
            for (int ks = 0; ks < 4; ks++) {
                ldsm4(sb + 0   + a_off + ks*32, qh[ks]);
                ldsm4(sb + AQB + a_off + ks*32, ql[ks]);
            }
        }

        float s[8][4];
        #pragma unroll
        for (int nj = 0; nj < 8; nj++)
            #pragma unroll
            for (int r = 0; r < 4; r++) s[nj][r] = 0.f;

        #pragma unroll
        for (int ks = 0; ks < 4; ks++) {
            uint32_t b[4][4];
            #pragma unroll
            for (int np = 0; np < 4; np++)
                ldsm4(stg + 0*AQB + ((b_row + np*16)*RSA + ks*16 + b_half)*2, b[np]);
            #pragma unroll
            for (int nj = 0; nj < 8; nj++) {
                uint32_t q0r = b[nj>>1][(nj&1)*2], q1r = b[nj>>1][(nj&1)*2+1];
                mma_bf16(s[nj], qh[ks][0], qh[ks][1], qh[ks][2], qh[ks][3], q0r, q1r);
                mma_bf16(s[nj], ql[ks][0], ql[ks][1], ql[ks][2], ql[ks][3], q0r, q1r);
            }
        }
        #pragma unroll
        for (int ks = 0; ks < 4; ks++) {
            uint32_t b[4][4];
            #pragma unroll
            for (int np = 0; np < 4; np++)
                ldsm4(stg + 1*AQB + ((b_row + np*16)*RSA + ks*16 + b_half)*2, b[np]);
            #pragma unroll
            for (int nj = 0; nj < 8; nj++)
                mma_bf16(s[nj], qh[ks][0], qh[ks][1], qh[ks][2], qh[ks][3],
                         b[nj>>1][(nj&1)*2], b[nj>>1][(nj&1)*2+1]);
        }

        int k0 = (kt0 + it) * KT;
        if (h != 0) {
            #pragma unroll
            for (int nj = 0; nj < 8; nj++) {
                int c0 = k0 + nj*8 + 2*(lane & 3);
                if (abs(r0g - c0)     > LOCALK) s[nj][0] = NEGF;
                if (abs(r0g - c0 - 1) > LOCALK) s[nj][1] = NEGF;
                if (abs(r0g + 8 - c0)     > LOCALK) s[nj][2] = NEGF;
                if (abs(r0g + 8 - c0 - 1) > LOCALK) s[nj][3] = NEGF;
            }
        }

        float mx0 = NEGF, mx1 = NEGF;
        #pragma unroll
        for (int nj = 0; nj < 8; nj++) {
            mx0 = fmaxf(mx0, fmaxf(s[nj][0], s[nj][1]));
            mx1 = fmaxf(mx1, fmaxf(s[nj][2], s[nj][3]));
        }
        mx0 = fmaxf(mx0, __shfl_xor_sync(0xffffffffu, mx0, 1));
        mx0 = fmaxf(mx0, __shfl_xor_sync(0xffffffffu, mx0, 2));
        mx1 = fmaxf(mx1, __shfl_xor_sync(0xffffffffu, mx1, 1));
        mx1 = fmaxf(mx1, __shfl_xor_sync(0xffffffffu, mx1, 2));
        float nm0 = fmaxf(m0, mx0), nm1 = fmaxf(m1, mx1);
        float cr0 = __expf(m0 - nm0), cr1 = __expf(m1 - nm1);
        m0 = nm0; m1 = nm1; l0 *= cr0; l1 *= cr1;
        #pragma unroll
        for (int nj = 0; nj < 8; nj++) {
            o[nj][0] *= cr0; o[nj][1] *= cr0;
            o[nj][2] *= cr1; o[nj][3] *= cr1;
        }
        float rs0 = 0.f, rs1 = 0.f;
        #pragma unroll
        for (int nj = 0; nj < 8; nj++) {
            float p0 = __expf(s[nj][0] - m0), p1 = __expf(s[nj][1] - m0);
            float p2 = __expf(s[nj][2] - m1), p3 = __expf(s[nj][3] - m1);
            rs0 += p0 + p1; rs1 += p2 + p3;
            uint32_t h01 = prmt_hi(p0, p1), h23 = prmt_hi(p2, p3);
            uint32_t lo01 = packbf(p0 - truncbf(p0), p1 - truncbf(p1));
            uint32_t lo23 = packbf(p2 - truncbf(p2), p3 - truncbf(p3));
            s[nj][0] = __uint_as_float(h01);  s[nj][1] = __uint_as_float(h23);
            s[nj][2] = __uint_as_float(lo01); s[nj][3] = __uint_as_float(lo23);
        }
        rs0 += __shfl_xor_sync(0xffffffffu, rs0, 1);
        rs0 += __shfl_xor_sync(0xffffffffu, rs0, 2);
        rs1 += __shfl_xor_sync(0xffffffffu, rs1, 1);
        rs1 += __shfl_xor_sync(0xffffffffu, rs1, 2);
        l0 += rs0; l1 += rs1;

        #pragma unroll
        for (int kc = 0; kc < 4; kc++) {
            uint32_t ah0 = __float_as_uint(s[2*kc][0]),   ah1 = __float_as_uint(s[2*kc][1]);
            uint32_t ah2 = __float_as_uint(s[2*kc+1][0]), ah3 = __float_as_uint(s[2*kc+1][1]);
            uint32_t al0 = __float_as_uint(s[2*kc][2]),   al1 = __float_as_uint(s[2*kc][3]);
            uint32_t al2 = __float_as_uint(s[2*kc+1][2]), al3 = __float_as_uint(s[2*kc+1][3]);
            uint32_t b[4][4];
            #pragma unroll
            for (int np = 0; np < 4; np++)
                ldsm4(stg + 2*AQB + ((b_row + np*16)*RSA + kc*16 + b_half)*2, b[np]);
            #pragma unroll
            for (int nj = 0; nj < 8; nj++) {
                uint32_t q0r = b[nj>>1][(nj&1)*2], q1r = b[nj>>1][(nj&1)*2+1];
                mma_bf16(o[nj], ah0, ah1, ah2, ah3, q0r, q1r);
                mma_bf16(o[nj], al0, al1, al2, al3, q0r, q1r);
            }
            #pragma unroll
            for (int np = 0; np < 4; np++)
                ldsm4(stg + 3*AQB + ((b_row + np*16)*RSA + kc*16 + b_half)*2, b[np]);
            #pragma unroll
            for (int nj = 0; nj < 8; nj++)
                mma_bf16(o[nj], ah0, ah1, ah2, ah3,
                         b[nj>>1][(nj&1)*2], b[nj>>1][(nj&1)*2+1]);
        }
        __syncthreads();
    }

    // Epilogue: normalize, fp16 split, store
    float inv0 = 1.f / l0, inv1 = 1.f / l1;
    #pragma unroll
    for (int nj = 0; nj < 8; nj++) {
        int d = nj*8 + 2*(lane & 3);
        float v0 = o[nj][0]*inv0, v1 = o[nj][1]*inv0;
        float v2 = o[nj][2]*inv1, v3 = o[nj][3]*inv1;
        __half h0 = __float2half_rn(v0), h1 = __float2half_rn(v1);
        __half h2 = __float2half_rn(v2), h3 = __float2half_rn(v3);
        __half r0 = __float2half_rn(v0 - __half2float(h0));
        __half r1 = __float2half_rn(v1 - __half2float(h1));
        __half r2 = __float2half_rn(v2 - __half2float(h2));
        __half r3 = __float2half_rn(v3 - __half2float(h3));
        size_t base0 = ((size_t)(bb*SEQ + r0g)) * EMB + h*HD + d;
        size_t base1 = ((size_t)(bb*SEQ + r0g + 8)) * EMB + h*HD + d;
        *(__half2*)(g_ahi + base0) = __halves2half2(h0, h1);
        *(__half2*)(g_alo + base0) = __halves2half2(r0, r1);
        *(__half2*)(g_ahi + base1) = __halves2half2(h2, h3);
        *(__half2*)(g_alo + base1) = __halves2half2(r2, r3);
    }
}

// ============================================================================
// Launch
// ============================================================================
extern "C" void kernel_launch(void* const* d_in, const int* in_sizes, int n_in,
                              void* d_out, int out_size)
{
    (void)in_sizes; (void)n_in; (void)out_size;
    const float* x  = (const float*)d_in[0];
    const float* wq = (const float*)d_in[1];
    const float* bq = (const float*)d_in[2];
    const float* wk = (const float*)d_in[3];
    const float* bk = (const float*)d_in[4];
    const float* wv = (const float*)d_in[5];
    const float* bv = (const float*)d_in[6];
    const float* wo = (const float*)d_in[7];
    const float* bo = (const float*)d_in[8];
    float* out = (float*)d_out;

    cudaFuncSetAttribute(gemm_hmma, cudaFuncAttributeMaxDynamicSharedMemorySize, GSMEM);
    cudaFuncSetAttribute(attn_tc,   cudaFuncAttributeMaxDynamicSharedMemorySize, ASMEM);

    split_kernel<<<SZ/4/256, 256>>>(x,  0, SZ/4);
    split_kernel<<<EMB*EMB/4/256, 256>>>(wq, 1, EMB*EMB/4);
    split_kernel<<<EMB*EMB/4/256, 256>>>(wk, 2, EMB*EMB/4);
    split_kernel<<<EMB*EMB/4/256, 256>>>(wv, 3, EMB*EMB/4);
    split_kernel<<<EMB*EMB/4/256, 256>>>(wo, 4, EMB*EMB/4);

    // Fused QKV: grid.x = 3 weights x 8 N-tiles
    gemm_hmma<<<dim3(24, 64), 256, GSMEM>>>(bq, bk, bv, nullptr, 0, 1);

    attn_tc<<<dim3(SEQ/QT, B_*NH), 128, ASMEM>>>();

    // O projection
    gemm_hmma<<<dim3(8, 64), 256, GSMEM>>>(bo, nullptr, nullptr, out, 1, 0);
}